// round 7
// baseline (speedup 1.0000x reference)
#include <cuda_runtime.h>
#include <math.h>

#define NNODE 1000
#define TT 12
#define BB 32
#define BT 384
#define CC 96
#define HG 192
#define G3 576
#define BNR 32000
#define DA 32
#define DE 10
#define HOR 12
#define LN_EPS 1e-5f

// ---------------- consolidated big scratch (offsets in floats) ----------------
// Layout:
//   HS  : [0,                 36,864,000)   BNR*TT*CC   — GCN out (raw-view layout), GRU0 input
//   XP  : [36,864,000,        258,048,000)  BNR*TT*G3   — gate preactivations (reused by both GRU layers)
//         (GCN phase aliases: H = XP+0 (36.9M), Z = XP+36,864,000 (36.9M) — dead before XP first written)
//   ys0 : [258,048,000,       331,776,000)  BNR*TT*HG
//   ys1 : [331,776,000,       405,504,000)  BNR*TT*HG
#define OFF_HS  ((size_t)0)
#define OFF_XP  ((size_t)36864000)
#define OFF_H   (OFF_XP)
#define OFF_Z   (OFF_XP + (size_t)36864000)
#define OFF_YS0 ((size_t)258048000)
#define OFF_YS1 ((size_t)331776000)
#define BIG_FLOATS ((size_t)405504000)
__device__ float g_big[BIG_FLOATS];

__device__ float g_Aadp[NNODE*NNODE];
__device__ float g_S[NNODE*NNODE];
__device__ float g_rs[3*NNODE];
__device__ float g_Wt[NNODE*DA];
__device__ float g_P[4*NNODE*DA];
__device__ float g_scpart[3*NNODE];
__device__ float g_cons[8];
__device__ float g_dWc[CC];
__device__ float g_dbc[CC];
__device__ float g_dinv[NNODE];
__device__ float g_Y[BT*NNODE];
__device__ float g_zero[HG];            // never written: GRU h0
__device__ float g_Wih0p[G3*CC];
__device__ float g_Whh0p[G3*HG];
__device__ float g_Wih1p[G3*HG];
__device__ float g_Whh1p[G3*HG];
__device__ float g_bih0p[G3];
__device__ float g_bhh0p[G3];
__device__ float g_bih1p[G3];
__device__ float g_bhh1p[G3];
__device__ float g_fc1t[HG*HG];
__device__ float g_fc2t[HG*HOR];

__device__ __forceinline__ float sigf(float x){ return 1.0f/(1.0f+expf(-x)); }
__device__ __forceinline__ float gelu_t(float x){
    float x3 = x*x*x;
    return 0.5f*x*(1.0f + tanhf(0.7978845608028654f*(x + 0.044715f*x3)));
}

// ---------------- prep ----------------
__global__ void k_transp(const float* __restrict__ src, float* __restrict__ dst, int R, int C){
    int i = blockIdx.x*256 + threadIdx.x;
    if (i < R*C){ int r = i / C, c = i % C; dst[c*R + r] = src[i]; }
}

__global__ void k_rowsums(const float* __restrict__ A, const float* __restrict__ F, const float* __restrict__ D){
    __shared__ float red[256];
    int n = blockIdx.x, tid = threadIdx.x;
    float s[3] = {0.f,0.f,0.f};
    for (int m = tid; m < NNODE; m += 256){
        s[0] += A[n*NNODE+m]; s[1] += F[n*NNODE+m]; s[2] += D[n*NNODE+m];
    }
    for (int k = 0; k < 3; k++){
        red[tid] = s[k]; __syncthreads();
        for (int st = 128; st > 0; st >>= 1){ if (tid < st) red[tid] += red[tid+st]; __syncthreads(); }
        if (tid == 0) g_rs[k*NNODE+n] = red[0];
        __syncthreads();
    }
}

__global__ void k_adapt(const float* __restrict__ E1, const float* __restrict__ E2){
    __shared__ float e[NNODE];
    __shared__ float red[256];
    int n = blockIdx.x, tid = threadIdx.x;
    float e1[DE];
#pragma unroll
    for (int d = 0; d < DE; d++) e1[d] = E1[n*DE + d];
    float lmax = -1e30f;
    for (int m = tid; m < NNODE; m += 256){
        float dot = 0.f;
#pragma unroll
        for (int d = 0; d < DE; d++) dot += e1[d]*E2[m*DE + d];
        dot = fmaxf(dot, 0.f);
        e[m] = dot; lmax = fmaxf(lmax, dot);
    }
    red[tid] = lmax; __syncthreads();
    for (int st = 128; st > 0; st >>= 1){ if (tid < st) red[tid] = fmaxf(red[tid], red[tid+st]); __syncthreads(); }
    float mx = red[0]; __syncthreads();
    float ls = 0.f;
    for (int m = tid; m < NNODE; m += 256){ float ex = expf(e[m]-mx); e[m] = ex; ls += ex; }
    red[tid] = ls; __syncthreads();
    for (int st = 128; st > 0; st >>= 1){ if (tid < st) red[tid] += red[tid+st]; __syncthreads(); }
    float inv = 1.0f/red[0];
    for (int m = tid; m < NNODE; m += 256) g_Aadp[n*NNODE+m] = e[m]*inv;
}

__global__ void k_proj(const float* __restrict__ A, const float* __restrict__ F, const float* __restrict__ D){
    __shared__ float r[4][NNODE];
    int n = blockIdx.x, tid = threadIdx.x;  // 128 threads
    for (int m = tid; m < NNODE; m += 128){
        r[0][m] = A[n*NNODE+m]; r[1][m] = F[n*NNODE+m]; r[2][m] = D[n*NNODE+m]; r[3][m] = g_Aadp[n*NNODE+m];
    }
    __syncthreads();
    int w = tid >> 5, a = tid & 31;
    float acc = 0.f;
    for (int m = 0; m < NNODE; m++) acc += r[w][m]*g_Wt[m*DA + a];
    g_P[w*(NNODE*DA) + n*DA + a] = acc;
}

__global__ void k_scorepart(const float* __restrict__ fus_b, const float* __restrict__ fus_v,
                            const float* __restrict__ beta1, const float* __restrict__ beta2){
    int n = blockIdx.x, a = threadIdx.x; // 32 threads
    float w1 = sigf(beta1[0]), w2 = sigf(beta2[0]);
    float pA = g_P[0*NNODE*DA + n*DA + a];
    float pF = g_P[1*NNODE*DA + n*DA + a];
    float pD = g_P[2*NNODE*DA + n*DA + a];
    float pP = g_P[3*NNODE*DA + n*DA + a];
    float fb = fus_b[a], fv = fus_v[a];
    float t0 = tanhf(0.5f*pA + 0.5f*pP + fb)*fv;
    float t1 = tanhf(w1*pA + (1.f-w1)*pF + fb)*fv;
    float t2 = tanhf(w2*pA + (1.f-w2)*pD + fb)*fv;
#pragma unroll
    for (int s = 16; s > 0; s >>= 1){
        t0 += __shfl_down_sync(0xffffffffu, t0, s);
        t1 += __shfl_down_sync(0xffffffffu, t1, s);
        t2 += __shfl_down_sync(0xffffffffu, t2, s);
    }
    if (a == 0){ g_scpart[0*NNODE+n]=t0; g_scpart[1*NNODE+n]=t1; g_scpart[2*NNODE+n]=t2; }
}

__global__ void k_finalize(const float* __restrict__ beta1, const float* __restrict__ beta2,
                           const float* __restrict__ W1, const float* __restrict__ b1){
    __shared__ float red[1024];
    __shared__ float sc[3];
    __shared__ float st[6];
    int tid = threadIdx.x;
    for (int k = 0; k < 3; k++){
        red[tid] = (tid < NNODE) ? g_scpart[k*NNODE + tid] : 0.f;
        __syncthreads();
        for (int s = 512; s > 0; s >>= 1){ if (tid < s) red[tid] += red[tid+s]; __syncthreads(); }
        if (tid == 0) sc[k] = red[0] / (float)NNODE;
        __syncthreads();
    }
    red[tid] = (tid < CC) ? W1[tid] : 0.f; __syncthreads();
    for (int s = 512; s > 0; s >>= 1){ if (tid < s) red[tid] += red[tid+s]; __syncthreads(); }
    if (tid == 0) st[0] = red[0]/(float)CC;
    __syncthreads();
    red[tid] = (tid < CC) ? b1[tid] : 0.f; __syncthreads();
    for (int s = 512; s > 0; s >>= 1){ if (tid < s) red[tid] += red[tid+s]; __syncthreads(); }
    if (tid == 0) st[1] = red[0]/(float)CC;
    __syncthreads();
    float dw = 0.f, db = 0.f;
    if (tid < CC){
        dw = W1[tid] - st[0]; db = b1[tid] - st[1];
        g_dWc[tid] = dw; g_dbc[tid] = db;
    }
    red[tid] = dw*dw; __syncthreads();
    for (int s = 512; s > 0; s >>= 1){ if (tid < s) red[tid] += red[tid+s]; __syncthreads(); }
    if (tid == 0) st[2] = red[0]/(float)CC;
    __syncthreads();
    red[tid] = dw*db; __syncthreads();
    for (int s = 512; s > 0; s >>= 1){ if (tid < s) red[tid] += red[tid+s]; __syncthreads(); }
    if (tid == 0) st[3] = red[0]/(float)CC;
    __syncthreads();
    red[tid] = db*db; __syncthreads();
    for (int s = 512; s > 0; s >>= 1){ if (tid < s) red[tid] += red[tid+s]; __syncthreads(); }
    if (tid == 0) st[4] = red[0]/(float)CC;
    __syncthreads();
    if (tid == 0){
        float w1 = sigf(beta1[0]), w2 = sigf(beta2[0]);
        float m = fmaxf(sc[0], fmaxf(sc[1], sc[2]));
        float e0 = expf(sc[0]-m), e1 = expf(sc[1]-m), e2 = expf(sc[2]-m);
        float is = 1.f/(e0+e1+e2);
        float a0 = e0*is, a1 = e1*is, a2 = e2*is;
        g_cons[0] = 0.5f*a0 + w1*a1 + w2*a2;
        g_cons[1] = a1*(1.f-w1);
        g_cons[2] = a2*(1.f-w2);
        g_cons[3] = 0.5f*a0;
        g_cons[4] = st[2];
        g_cons[5] = st[3];
        g_cons[6] = st[4];
    }
    __syncthreads();
    if (tid < NNODE){
        float d = g_cons[0]*g_rs[tid] + g_cons[1]*g_rs[NNODE+tid] + g_cons[2]*g_rs[2*NNODE+tid] + g_cons[3] + 1.0f;
        g_dinv[tid] = rsqrtf(fmaxf(d, 1e-12f));
    }
}

__global__ void k_shat(const float* __restrict__ A, const float* __restrict__ F, const float* __restrict__ D){
    int idx = blockIdx.x*256 + threadIdx.x;
    if (idx >= NNODE*NNODE) return;
    int n = idx / NNODE, m = idx - n*NNODE;
    float v = g_cons[0]*A[idx] + g_cons[1]*F[idx] + g_cons[2]*D[idx] + g_cons[3]*g_Aadp[idx];
    if (n == m) v += 1.0f;
    g_S[idx] = v * g_dinv[n]*g_dinv[m];
}

// permute GRU weights: original row g*HG+c -> row 3c+g
__global__ void k_permW(const float* __restrict__ W, const float* __restrict__ bi,
                        float* __restrict__ Wp, float* __restrict__ bp, int K){
    int idx = blockIdx.x*256 + threadIdx.x;
    if (idx < G3*K){
        int row = idx / K, k = idx - row*K;
        int g = row / HG, c = row - g*HG;
        Wp[(3*c+g)*K + k] = W[idx];
    }
    if (idx < G3){
        int g = idx / HG, c = idx - g*HG;
        bp[3*c+g] = bi[idx];
    }
}

// GCN layer1 elementwise (LN-of-affine-in-scalar trick)
__global__ void k_gcn1(const float* __restrict__ g1, const float* __restrict__ bln1,
                       float* __restrict__ H){
    int idx = blockIdx.x*256 + threadIdx.x;
    if (idx >= BT*NNODE*CC) return;
    int row = idx / CC, c = idx - row*CC;
    float y = __ldg(&g_Y[row]);
    float diff = y*g_dWc[c] + g_dbc[c];
    float var = y*y*g_cons[4] + 2.f*y*g_cons[5] + g_cons[6];
    float h = diff*rsqrtf(var + LN_EPS)*g1[c] + bln1[c];
    H[idx] = fmaxf(h, 0.f);
}

// ---------------- GEMMs: 64x96 tile, BK=32, 256 threads, 4x6 per thread ----------------
template<bool GUARD>
__global__ void k_gemm_nt(const float* __restrict__ A, int lda,
                          const float* __restrict__ B, int ldb,
                          float* __restrict__ C, int ldc,
                          int M, int N, int K, const float* __restrict__ bias){
    __shared__ float As[64][33];
    __shared__ float Bs[32][98];
    int tid = threadIdx.x;
    int tx = tid & 15, ty = tid >> 4;
    int m0 = blockIdx.y*64, n0 = blockIdx.x*96;
    float acc[4][6];
#pragma unroll
    for (int i = 0; i < 4; i++)
#pragma unroll
        for (int j = 0; j < 6; j++) acc[i][j] = 0.f;
    for (int k0 = 0; k0 < K; k0 += 32){
#pragma unroll
        for (int e = tid; e < 2048; e += 256){
            int r = e >> 5, c = e & 31;
            float v;
            if (GUARD) v = (m0+r < M && k0+c < K) ? A[(size_t)(m0+r)*lda + k0+c] : 0.f;
            else       v = A[(size_t)(m0+r)*lda + k0+c];
            As[r][c] = v;
        }
#pragma unroll
        for (int e = tid; e < 3072; e += 256){
            int j = e >> 5, c = e & 31;
            float v;
            if (GUARD) v = (n0+j < N && k0+c < K) ? B[(size_t)(n0+j)*ldb + k0+c] : 0.f;
            else       v = B[(size_t)(n0+j)*ldb + k0+c];
            Bs[c][j] = v;
        }
        __syncthreads();
#pragma unroll
        for (int kk = 0; kk < 32; kk++){
            float a[4], b[6];
#pragma unroll
            for (int i = 0; i < 4; i++) a[i] = As[ty*4+i][kk];
#pragma unroll
            for (int j = 0; j < 6; j++) b[j] = Bs[kk][tx*6+j];
#pragma unroll
            for (int i = 0; i < 4; i++)
#pragma unroll
                for (int j = 0; j < 6; j++) acc[i][j] += a[i]*b[j];
        }
        __syncthreads();
    }
#pragma unroll
    for (int i = 0; i < 4; i++){
        int gr = m0 + ty*4 + i;
        if (GUARD && gr >= M) continue;
#pragma unroll
        for (int j = 0; j < 6; j++){
            int gc = n0 + tx*6 + j;
            if (GUARD && gc >= N) continue;
            float v = acc[i][j];
            if (bias) v += bias[gc];
            C[(size_t)gr*ldc + gc] = v;
        }
    }
}

template<bool GUARD>
__global__ void k_gemm_nn(const float* __restrict__ A, int lda,
                          const float* __restrict__ Bbase, int ldb, int bstride,
                          float* __restrict__ Cbase, int ldc, int cstride,
                          int M, int N, int K){
    const float* B = Bbase + (size_t)blockIdx.z*bstride;
    float* C = Cbase + (size_t)blockIdx.z*cstride;
    __shared__ float As[64][33];
    __shared__ float Bs[32][98];
    int tid = threadIdx.x;
    int tx = tid & 15, ty = tid >> 4;
    int m0 = blockIdx.y*64, n0 = blockIdx.x*96;
    float acc[4][6];
#pragma unroll
    for (int i = 0; i < 4; i++)
#pragma unroll
        for (int j = 0; j < 6; j++) acc[i][j] = 0.f;
    for (int k0 = 0; k0 < K; k0 += 32){
#pragma unroll
        for (int e = tid; e < 2048; e += 256){
            int r = e >> 5, c = e & 31;
            float v;
            if (GUARD) v = (m0+r < M && k0+c < K) ? A[(size_t)(m0+r)*lda + k0+c] : 0.f;
            else       v = A[(size_t)(m0+r)*lda + k0+c];
            As[r][c] = v;
        }
#pragma unroll
        for (int e = tid; e < 3072; e += 256){
            int kk = e / 96, j = e - kk*96;
            float v;
            if (GUARD) v = (k0+kk < K && n0+j < N) ? B[(size_t)(k0+kk)*ldb + n0+j] : 0.f;
            else       v = B[(size_t)(k0+kk)*ldb + n0+j];
            Bs[kk][j] = v;
        }
        __syncthreads();
#pragma unroll
        for (int kk = 0; kk < 32; kk++){
            float a[4], b[6];
#pragma unroll
            for (int i = 0; i < 4; i++) a[i] = As[ty*4+i][kk];
#pragma unroll
            for (int j = 0; j < 6; j++) b[j] = Bs[kk][tx*6+j];
#pragma unroll
            for (int i = 0; i < 4; i++)
#pragma unroll
                for (int j = 0; j < 6; j++) acc[i][j] += a[i]*b[j];
        }
        __syncthreads();
    }
#pragma unroll
    for (int i = 0; i < 4; i++){
        int gr = m0 + ty*4 + i;
        if (GUARD && gr >= M) continue;
#pragma unroll
        for (int j = 0; j < 6; j++){
            int gc = n0 + tx*6 + j;
            if (GUARD && gc >= N) continue;
            C[(size_t)gr*ldc + gc] = acc[i][j];
        }
    }
}

// Z @ W2 + b2 -> LN(ln2) -> write in natural (b,t,n,c) order (raw-view reshape semantics)
__global__ void k_gemm_nn_ln(const float* __restrict__ A,   // Z, lda=96
                             const float* __restrict__ W2,  // 96x96
                             const float* __restrict__ b2,
                             const float* __restrict__ g2,
                             const float* __restrict__ bln2,
                             float* __restrict__ HS){
    __shared__ float As[64][33];
    __shared__ float Bs[32][98];
    __shared__ float red[64][17];
    int tid = threadIdx.x;
    int tx = tid & 15, ty = tid >> 4;
    int m0 = blockIdx.y*64;
    float acc[4][6];
#pragma unroll
    for (int i = 0; i < 4; i++)
#pragma unroll
        for (int j = 0; j < 6; j++) acc[i][j] = 0.f;
    for (int k0 = 0; k0 < 96; k0 += 32){
#pragma unroll
        for (int e = tid; e < 2048; e += 256){
            int r = e >> 5, c = e & 31;
            As[r][c] = A[(size_t)(m0+r)*96 + k0+c];
        }
#pragma unroll
        for (int e = tid; e < 3072; e += 256){
            int kk = e / 96, j = e - kk*96;
            Bs[kk][j] = W2[(k0+kk)*96 + j];
        }
        __syncthreads();
#pragma unroll
        for (int kk = 0; kk < 32; kk++){
            float a[4], b[6];
#pragma unroll
            for (int i = 0; i < 4; i++) a[i] = As[ty*4+i][kk];
#pragma unroll
            for (int j = 0; j < 6; j++) b[j] = Bs[kk][tx*6+j];
#pragma unroll
            for (int i = 0; i < 4; i++)
#pragma unroll
                for (int j = 0; j < 6; j++) acc[i][j] += a[i]*b[j];
        }
        __syncthreads();
    }
    float v[4][6];
#pragma unroll
    for (int i = 0; i < 4; i++)
#pragma unroll
        for (int j = 0; j < 6; j++) v[i][j] = acc[i][j] + b2[tx*6+j];
#pragma unroll
    for (int i = 0; i < 4; i++){
        float p = 0.f;
#pragma unroll
        for (int j = 0; j < 6; j++) p += v[i][j];
        red[ty*4+i][tx] = p;
    }
    __syncthreads();
    float mean[4];
#pragma unroll
    for (int i = 0; i < 4; i++){
        float s = 0.f;
#pragma unroll
        for (int q = 0; q < 16; q++) s += red[ty*4+i][q];
        mean[i] = s * (1.0f/96.0f);
    }
    __syncthreads();
#pragma unroll
    for (int i = 0; i < 4; i++){
        float p = 0.f;
#pragma unroll
        for (int j = 0; j < 6; j++){ float d = v[i][j]-mean[i]; p += d*d; }
        red[ty*4+i][tx] = p;
    }
    __syncthreads();
#pragma unroll
    for (int i = 0; i < 4; i++){
        float s = 0.f;
#pragma unroll
        for (int q = 0; q < 16; q++) s += red[ty*4+i][q];
        float rstd = rsqrtf(s*(1.0f/96.0f) + LN_EPS);
        int R = m0 + ty*4 + i;
        size_t base = (size_t)R*96;         // RAW VIEW: identity layout
#pragma unroll
        for (int j = 0; j < 6; j++){
            int col = tx*6 + j;
            HS[base + col] = (v[i][j]-mean[i])*rstd*g2[col] + bln2[col];
        }
    }
}

// GRU recurrent step: hp = h_prev @ Whhp^T (+bhh in epilogue), fused gates.
__global__ void k_gru_step(const float* __restrict__ A, int lda,
                           const float* __restrict__ B,      // Whhp 576x192
                           const float* __restrict__ xp,     // + t*576, row stride 6912
                           const float* __restrict__ bhh,    // permuted
                           float* __restrict__ ys){          // + t*192, row stride 2304
    __shared__ float As[64][33];
    __shared__ float Bs[32][98];
    int tid = threadIdx.x;
    int tx = tid & 15, ty = tid >> 4;
    int m0 = blockIdx.y*64, n0 = blockIdx.x*96;
    float acc[4][6];
#pragma unroll
    for (int i = 0; i < 4; i++)
#pragma unroll
        for (int j = 0; j < 6; j++) acc[i][j] = 0.f;
    for (int k0 = 0; k0 < 192; k0 += 32){
#pragma unroll
        for (int e = tid; e < 2048; e += 256){
            int r = e >> 5, c = e & 31;
            As[r][c] = A[(size_t)(m0+r)*lda + k0+c];
        }
#pragma unroll
        for (int e = tid; e < 3072; e += 256){
            int j = e >> 5, c = e & 31;
            Bs[c][j] = B[(size_t)(n0+j)*192 + k0+c];
        }
        __syncthreads();
#pragma unroll
        for (int kk = 0; kk < 32; kk++){
            float a[4], b[6];
#pragma unroll
            for (int i = 0; i < 4; i++) a[i] = As[ty*4+i][kk];
#pragma unroll
            for (int j = 0; j < 6; j++) b[j] = Bs[kk][tx*6+j];
#pragma unroll
            for (int i = 0; i < 4; i++)
#pragma unroll
                for (int j = 0; j < 6; j++) acc[i][j] += a[i]*b[j];
        }
        __syncthreads();
    }
    int j0 = n0 + tx*6;
    int c0 = j0 / 3;
#pragma unroll
    for (int i = 0; i < 4; i++){
        int row = m0 + ty*4 + i;
        const float* xr = xp + (size_t)row*6912;
#pragma unroll
        for (int p = 0; p < 2; p++){
            int j = j0 + p*3;
            int c = c0 + p;
            float hprev = A[(size_t)row*lda + c];   // lda=0 -> g_zero[c]=0 at t=0
            float r = sigf(xr[j]   + acc[i][p*3]   + bhh[j]);
            float z = sigf(xr[j+1] + acc[i][p*3+1] + bhh[j+1]);
            float nn = tanhf(xr[j+2] + r*(acc[i][p*3+2] + bhh[j+2]));
            ys[(size_t)row*2304 + c] = (1.f-z)*nn + z*hprev;
        }
    }
}

// Attention pooling + FC head
__global__ void k_pool(const float* __restrict__ ys, const float* __restrict__ attw,
                       const float* __restrict__ fc1b, const float* __restrict__ fc2b,
                       float* __restrict__ out){
    __shared__ float sOut[12][193];
    __shared__ float sAtt[12];
    __shared__ float sCtx[192];
    __shared__ float sHfc[192];
    __shared__ float red2[16][12];
    int bn = blockIdx.x, tid = threadIdx.x;  // 192 threads
#pragma unroll
    for (int t = 0; t < 12; t++) sOut[t][tid] = ys[(size_t)bn*2304 + t*192 + tid];
    __syncthreads();
    int w = tid >> 5, l = tid & 31;
#pragma unroll
    for (int q = 0; q < 2; q++){
        int t = 2*w + q;
        float p = 0.f;
#pragma unroll
        for (int s = 0; s < 6; s++) p += sOut[t][l + 32*s]*attw[l + 32*s];
#pragma unroll
        for (int s = 16; s > 0; s >>= 1) p += __shfl_down_sync(0xffffffffu, p, s);
        if (l == 0) sAtt[t] = p;
    }
    __syncthreads();
    if (tid == 0){
        float mx = -1e30f;
        for (int t = 0; t < 12; t++) mx = fmaxf(mx, sAtt[t]);
        float s = 0.f;
        for (int t = 0; t < 12; t++){ sAtt[t] = expf(sAtt[t]-mx); s += sAtt[t]; }
        float inv = 1.f/s;
        for (int t = 0; t < 12; t++) sAtt[t] *= inv;
    }
    __syncthreads();
    float c = 0.f;
#pragma unroll
    for (int t = 0; t < 12; t++) c += sAtt[t]*sOut[t][tid];
    sCtx[tid] = c;
    __syncthreads();
    float a = fc1b[tid];
    for (int k = 0; k < 192; k++) a += sCtx[k]*g_fc1t[k*192 + tid];
    sHfc[tid] = gelu_t(a);
    __syncthreads();
    int o = tid % 12, grp = tid / 12;
    float p2 = 0.f;
    for (int j = grp; j < 192; j += 16) p2 += sHfc[j]*g_fc2t[j*12 + o];
    red2[grp][o] = p2;
    __syncthreads();
    if (tid < 12){
        float s = fc2b[tid];
#pragma unroll
        for (int q = 0; q < 16; q++) s += red2[q][tid];
        int b = bn / 1000, n = bn - b*1000;
        out[(size_t)(b*12 + tid)*1000 + n] = s;
    }
}

// ---------------- host launcher ----------------
extern "C" void kernel_launch(void* const* d_in, const int* in_sizes, int n_in,
                              void* d_out, int out_size){
    const float* x      = (const float*)d_in[0];
    const float* A      = (const float*)d_in[1];
    const float* FSP    = (const float*)d_in[2];
    const float* DSP    = (const float*)d_in[3];
    const float* E1     = (const float*)d_in[4];
    const float* E2     = (const float*)d_in[5];
    const float* fus_W  = (const float*)d_in[6];
    const float* fus_b  = (const float*)d_in[7];
    const float* fus_v  = (const float*)d_in[8];
    const float* beta1  = (const float*)d_in[9];
    const float* beta2  = (const float*)d_in[10];
    const float* gcn_W1 = (const float*)d_in[11];
    const float* gcn_b1 = (const float*)d_in[12];
    const float* ln1_g  = (const float*)d_in[13];
    const float* ln1_b  = (const float*)d_in[14];
    const float* gcn_W2 = (const float*)d_in[15];
    const float* gcn_b2 = (const float*)d_in[16];
    const float* ln2_g  = (const float*)d_in[17];
    const float* ln2_b  = (const float*)d_in[18];
    const float* Wih0   = (const float*)d_in[19];
    const float* Whh0   = (const float*)d_in[20];
    const float* bih0   = (const float*)d_in[21];
    const float* bhh0   = (const float*)d_in[22];
    const float* Wih1   = (const float*)d_in[23];
    const float* Whh1   = (const float*)d_in[24];
    const float* bih1   = (const float*)d_in[25];
    const float* bhh1   = (const float*)d_in[26];
    const float* att_w  = (const float*)d_in[27];
    const float* fc1_W  = (const float*)d_in[28];
    const float* fc1_b  = (const float*)d_in[29];
    const float* fc2_W  = (const float*)d_in[30];
    const float* fc2_b  = (const float*)d_in[31];
    float* out = (float*)d_out;

    float *p_big, *p_Wt, *p_S, *p_Y, *p_zero;
    float *p_Wih0p, *p_Whh0p, *p_Wih1p, *p_Whh1p, *p_bih0p, *p_bhh0p, *p_bih1p, *p_bhh1p;
    float *p_fc1t, *p_fc2t;
    cudaGetSymbolAddress((void**)&p_big, g_big);
    cudaGetSymbolAddress((void**)&p_Wt, g_Wt);
    cudaGetSymbolAddress((void**)&p_S, g_S);
    cudaGetSymbolAddress((void**)&p_Y, g_Y);
    cudaGetSymbolAddress((void**)&p_zero, g_zero);
    cudaGetSymbolAddress((void**)&p_Wih0p, g_Wih0p);
    cudaGetSymbolAddress((void**)&p_Whh0p, g_Whh0p);
    cudaGetSymbolAddress((void**)&p_Wih1p, g_Wih1p);
    cudaGetSymbolAddress((void**)&p_Whh1p, g_Whh1p);
    cudaGetSymbolAddress((void**)&p_bih0p, g_bih0p);
    cudaGetSymbolAddress((void**)&p_bhh0p, g_bhh0p);
    cudaGetSymbolAddress((void**)&p_bih1p, g_bih1p);
    cudaGetSymbolAddress((void**)&p_bhh1p, g_bhh1p);
    cudaGetSymbolAddress((void**)&p_fc1t, g_fc1t);
    cudaGetSymbolAddress((void**)&p_fc2t, g_fc2t);

    float* p_HS  = p_big + OFF_HS;
    float* p_XP  = p_big + OFF_XP;
    float* p_H   = p_big + OFF_H;
    float* p_Z   = p_big + OFF_Z;
    float* p_ys0 = p_big + OFF_YS0;
    float* p_ys1 = p_big + OFF_YS1;

    // graph construction
    k_transp<<<(DA*NNODE+255)/256, 256>>>(fus_W, p_Wt, DA, NNODE);
    k_rowsums<<<NNODE, 256>>>(A, FSP, DSP);
    k_adapt<<<NNODE, 256>>>(E1, E2);
    k_proj<<<NNODE, 128>>>(A, FSP, DSP);
    k_scorepart<<<NNODE, 32>>>(fus_b, fus_v, beta1, beta2);
    k_finalize<<<1, 1024>>>(beta1, beta2, gcn_W1, gcn_b1);
    k_shat<<<(NNODE*NNODE+255)/256, 256>>>(A, FSP, DSP);

    // weight prep
    k_permW<<<(G3*CC+255)/256, 256>>>(Wih0, bih0, p_Wih0p, p_bih0p, CC);
    k_permW<<<(G3*HG+255)/256, 256>>>(Whh0, bhh0, p_Whh0p, p_bhh0p, HG);
    k_permW<<<(G3*HG+255)/256, 256>>>(Wih1, bih1, p_Wih1p, p_bih1p, HG);
    k_permW<<<(G3*HG+255)/256, 256>>>(Whh1, bhh1, p_Whh1p, p_bhh1p, HG);
    k_transp<<<(HG*HG+255)/256, 256>>>(fc1_W, p_fc1t, HG, HG);
    k_transp<<<(HOR*HG+255)/256, 256>>>(fc2_W, p_fc2t, HOR, HG);

    // GCN
    {   dim3 g((NNODE+95)/96, (BT+63)/64);
        k_gemm_nt<true><<<g, 256>>>(x, NNODE, p_S, NNODE, p_Y, NNODE, BT, NNODE, NNODE, nullptr);
    }
    k_gcn1<<<(BT*NNODE*CC+255)/256, 256>>>(ln1_g, ln1_b, p_H);
    {   dim3 g(1, (NNODE+63)/64, BT);
        k_gemm_nn<true><<<g, 256>>>(p_S, NNODE, p_H, CC, NNODE*CC, p_Z, CC, NNODE*CC, NNODE, CC, NNODE);
    }
    {   dim3 g(1, (BT*NNODE)/64);
        k_gemm_nn_ln<<<g, 256>>>(p_Z, gcn_W2, gcn_b2, ln2_g, ln2_b, p_HS);
    }

    // GRU layer 0
    {   dim3 g(G3/96, (BNR*TT)/64);
        k_gemm_nt<false><<<g, 256>>>(p_HS, CC, p_Wih0p, CC, p_XP, G3, BNR*TT, G3, CC, p_bih0p);
    }
    for (int t = 0; t < TT; t++){
        const float* hA = (t == 0) ? p_zero : (p_ys0 + (size_t)(t-1)*HG);
        int lda = (t == 0) ? 0 : TT*HG;
        dim3 g(G3/96, BNR/64);
        k_gru_step<<<g, 256>>>(hA, lda, p_Whh0p, p_XP + (size_t)t*G3, p_bhh0p, p_ys0 + (size_t)t*HG);
    }
    // GRU layer 1
    {   dim3 g(G3/96, (BNR*TT)/64);
        k_gemm_nt<false><<<g, 256>>>(p_ys0, HG, p_Wih1p, HG, p_XP, G3, BNR*TT, G3, HG, p_bih1p);
    }
    for (int t = 0; t < TT; t++){
        const float* hA = (t == 0) ? p_zero : (p_ys1 + (size_t)(t-1)*HG);
        int lda = (t == 0) ? 0 : TT*HG;
        dim3 g(G3/96, BNR/64);
        k_gru_step<<<g, 256>>>(hA, lda, p_Whh1p, p_XP + (size_t)t*G3, p_bhh1p, p_ys1 + (size_t)t*HG);
    }

    // pooling + head
    k_pool<<<BNR, 192>>>(p_ys1, att_w, fc1_b, fc2_b, out);
}

// round 11
// speedup vs baseline: 1.3744x; 1.3744x over previous
#include <cuda_runtime.h>
#include <math.h>

#define NNODE 1000
#define TT 12
#define BB 32
#define BT 384
#define CC 96
#define HG 192
#define G3 576
#define BNR 32000
#define DA 32
#define DE 10
#define HOR 12
#define LN_EPS 1e-5f

// ---------------- consolidated big scratch (offsets in floats) ----------------
#define OFF_HS  ((size_t)0)
#define OFF_XP  ((size_t)36864000)
#define OFF_H   (OFF_XP)
#define OFF_Z   (OFF_XP + (size_t)36864000)
#define OFF_YS0 ((size_t)258048000)
#define OFF_YS1 ((size_t)331776000)
#define BIG_FLOATS ((size_t)405504000)
__device__ float g_big[BIG_FLOATS];

__device__ float g_Aadp[NNODE*NNODE];
__device__ float g_S[NNODE*NNODE];
__device__ float g_rs[3*NNODE];
__device__ float g_Wt[NNODE*DA];
__device__ float g_P[4*NNODE*DA];
__device__ float g_scpart[3*NNODE];
__device__ float g_cons[8];
__device__ float g_dWc[CC];
__device__ float g_dbc[CC];
__device__ float g_dinv[NNODE];
__device__ float g_Y[BT*NNODE];
__device__ float g_zero[HG];            // never written: GRU h0
__device__ float g_Wih0p[G3*CC];
__device__ float g_Whh0p[G3*HG];
__device__ float g_Wih1p[G3*HG];
__device__ float g_Whh1p[G3*HG];
__device__ float g_bih0p[G3];
__device__ float g_bhh0p[G3];
__device__ float g_bih1p[G3];
__device__ float g_bhh1p[G3];
__device__ float g_fc1t[HG*HG];
__device__ float g_fc2t[HG*HOR];

__device__ __forceinline__ float sigf(float x){ return 1.0f/(1.0f+expf(-x)); }
__device__ __forceinline__ float gelu_t(float x){
    float x3 = x*x*x;
    return 0.5f*x*(1.0f + tanhf(0.7978845608028654f*(x + 0.044715f*x3)));
}

// ---------------- packed f32x2 helpers (sm_103a FFMA2) ----------------
__device__ __forceinline__ unsigned long long pack2dup(float a){
    unsigned long long r;
    asm("mov.b64 %0, {%1, %1};" : "=l"(r) : "f"(a));
    return r;
}
__device__ __forceinline__ void fma2(unsigned long long& d, unsigned long long a, unsigned long long b){
    asm("fma.rn.f32x2 %0, %1, %2, %0;" : "+l"(d) : "l"(a), "l"(b));
}
__device__ __forceinline__ void unpack2(unsigned long long v, float& lo, float& hi){
    asm("mov.b64 {%0, %1}, %2;" : "=f"(lo), "=f"(hi) : "l"(v));
}

// ---------------- prep ----------------
__global__ void k_transp(const float* __restrict__ src, float* __restrict__ dst, int R, int C){
    int i = blockIdx.x*256 + threadIdx.x;
    if (i < R*C){ int r = i / C, c = i % C; dst[c*R + r] = src[i]; }
}

__global__ void k_rowsums(const float* __restrict__ A, const float* __restrict__ F, const float* __restrict__ D){
    __shared__ float red[256];
    int n = blockIdx.x, tid = threadIdx.x;
    float s[3] = {0.f,0.f,0.f};
    for (int m = tid; m < NNODE; m += 256){
        s[0] += A[n*NNODE+m]; s[1] += F[n*NNODE+m]; s[2] += D[n*NNODE+m];
    }
    for (int k = 0; k < 3; k++){
        red[tid] = s[k]; __syncthreads();
        for (int st = 128; st > 0; st >>= 1){ if (tid < st) red[tid] += red[tid+st]; __syncthreads(); }
        if (tid == 0) g_rs[k*NNODE+n] = red[0];
        __syncthreads();
    }
}

__global__ void k_adapt(const float* __restrict__ E1, const float* __restrict__ E2){
    __shared__ float e[NNODE];
    __shared__ float red[256];
    int n = blockIdx.x, tid = threadIdx.x;
    float e1[DE];
#pragma unroll
    for (int d = 0; d < DE; d++) e1[d] = E1[n*DE + d];
    float lmax = -1e30f;
    for (int m = tid; m < NNODE; m += 256){
        float dot = 0.f;
#pragma unroll
        for (int d = 0; d < DE; d++) dot += e1[d]*E2[m*DE + d];
        dot = fmaxf(dot, 0.f);
        e[m] = dot; lmax = fmaxf(lmax, dot);
    }
    red[tid] = lmax; __syncthreads();
    for (int st = 128; st > 0; st >>= 1){ if (tid < st) red[tid] = fmaxf(red[tid], red[tid+st]); __syncthreads(); }
    float mx = red[0]; __syncthreads();
    float ls = 0.f;
    for (int m = tid; m < NNODE; m += 256){ float ex = expf(e[m]-mx); e[m] = ex; ls += ex; }
    red[tid] = ls; __syncthreads();
    for (int st = 128; st > 0; st >>= 1){ if (tid < st) red[tid] += red[tid+st]; __syncthreads(); }
    float inv = 1.0f/red[0];
    for (int m = tid; m < NNODE; m += 256) g_Aadp[n*NNODE+m] = e[m]*inv;
}

__global__ void k_proj(const float* __restrict__ A, const float* __restrict__ F, const float* __restrict__ D){
    __shared__ float r[4][NNODE];
    int n = blockIdx.x, tid = threadIdx.x;  // 128 threads
    for (int m = tid; m < NNODE; m += 128){
        r[0][m] = A[n*NNODE+m]; r[1][m] = F[n*NNODE+m]; r[2][m] = D[n*NNODE+m]; r[3][m] = g_Aadp[n*NNODE+m];
    }
    __syncthreads();
    int w = tid >> 5, a = tid & 31;
    float acc = 0.f;
    for (int m = 0; m < NNODE; m++) acc += r[w][m]*g_Wt[m*DA + a];
    g_P[w*(NNODE*DA) + n*DA + a] = acc;
}

__global__ void k_scorepart(const float* __restrict__ fus_b, const float* __restrict__ fus_v,
                            const float* __restrict__ beta1, const float* __restrict__ beta2){
    int n = blockIdx.x, a = threadIdx.x; // 32 threads
    float w1 = sigf(beta1[0]), w2 = sigf(beta2[0]);
    float pA = g_P[0*NNODE*DA + n*DA + a];
    float pF = g_P[1*NNODE*DA + n*DA + a];
    float pD = g_P[2*NNODE*DA + n*DA + a];
    float pP = g_P[3*NNODE*DA + n*DA + a];
    float fb = fus_b[a], fv = fus_v[a];
    float t0 = tanhf(0.5f*pA + 0.5f*pP + fb)*fv;
    float t1 = tanhf(w1*pA + (1.f-w1)*pF + fb)*fv;
    float t2 = tanhf(w2*pA + (1.f-w2)*pD + fb)*fv;
#pragma unroll
    for (int s = 16; s > 0; s >>= 1){
        t0 += __shfl_down_sync(0xffffffffu, t0, s);
        t1 += __shfl_down_sync(0xffffffffu, t1, s);
        t2 += __shfl_down_sync(0xffffffffu, t2, s);
    }
    if (a == 0){ g_scpart[0*NNODE+n]=t0; g_scpart[1*NNODE+n]=t1; g_scpart[2*NNODE+n]=t2; }
}

__global__ void k_finalize(const float* __restrict__ beta1, const float* __restrict__ beta2,
                           const float* __restrict__ W1, const float* __restrict__ b1){
    __shared__ float red[1024];
    __shared__ float sc[3];
    __shared__ float st[6];
    int tid = threadIdx.x;
    for (int k = 0; k < 3; k++){
        red[tid] = (tid < NNODE) ? g_scpart[k*NNODE + tid] : 0.f;
        __syncthreads();
        for (int s = 512; s > 0; s >>= 1){ if (tid < s) red[tid] += red[tid+s]; __syncthreads(); }
        if (tid == 0) sc[k] = red[0] / (float)NNODE;
        __syncthreads();
    }
    red[tid] = (tid < CC) ? W1[tid] : 0.f; __syncthreads();
    for (int s = 512; s > 0; s >>= 1){ if (tid < s) red[tid] += red[tid+s]; __syncthreads(); }
    if (tid == 0) st[0] = red[0]/(float)CC;
    __syncthreads();
    red[tid] = (tid < CC) ? b1[tid] : 0.f; __syncthreads();
    for (int s = 512; s > 0; s >>= 1){ if (tid < s) red[tid] += red[tid+s]; __syncthreads(); }
    if (tid == 0) st[1] = red[0]/(float)CC;
    __syncthreads();
    float dw = 0.f, db = 0.f;
    if (tid < CC){
        dw = W1[tid] - st[0]; db = b1[tid] - st[1];
        g_dWc[tid] = dw; g_dbc[tid] = db;
    }
    red[tid] = dw*dw; __syncthreads();
    for (int s = 512; s > 0; s >>= 1){ if (tid < s) red[tid] += red[tid+s]; __syncthreads(); }
    if (tid == 0) st[2] = red[0]/(float)CC;
    __syncthreads();
    red[tid] = dw*db; __syncthreads();
    for (int s = 512; s > 0; s >>= 1){ if (tid < s) red[tid] += red[tid+s]; __syncthreads(); }
    if (tid == 0) st[3] = red[0]/(float)CC;
    __syncthreads();
    red[tid] = db*db; __syncthreads();
    for (int s = 512; s > 0; s >>= 1){ if (tid < s) red[tid] += red[tid+s]; __syncthreads(); }
    if (tid == 0) st[4] = red[0]/(float)CC;
    __syncthreads();
    if (tid == 0){
        float w1 = sigf(beta1[0]), w2 = sigf(beta2[0]);
        float m = fmaxf(sc[0], fmaxf(sc[1], sc[2]));
        float e0 = expf(sc[0]-m), e1 = expf(sc[1]-m), e2 = expf(sc[2]-m);
        float is = 1.f/(e0+e1+e2);
        float a0 = e0*is, a1 = e1*is, a2 = e2*is;
        g_cons[0] = 0.5f*a0 + w1*a1 + w2*a2;
        g_cons[1] = a1*(1.f-w1);
        g_cons[2] = a2*(1.f-w2);
        g_cons[3] = 0.5f*a0;
        g_cons[4] = st[2];
        g_cons[5] = st[3];
        g_cons[6] = st[4];
    }
    __syncthreads();
    if (tid < NNODE){
        float d = g_cons[0]*g_rs[tid] + g_cons[1]*g_rs[NNODE+tid] + g_cons[2]*g_rs[2*NNODE+tid] + g_cons[3] + 1.0f;
        g_dinv[tid] = rsqrtf(fmaxf(d, 1e-12f));
    }
}

__global__ void k_shat(const float* __restrict__ A, const float* __restrict__ F, const float* __restrict__ D){
    int idx = blockIdx.x*256 + threadIdx.x;
    if (idx >= NNODE*NNODE) return;
    int n = idx / NNODE, m = idx - n*NNODE;
    float v = g_cons[0]*A[idx] + g_cons[1]*F[idx] + g_cons[2]*D[idx] + g_cons[3]*g_Aadp[idx];
    if (n == m) v += 1.0f;
    g_S[idx] = v * g_dinv[n]*g_dinv[m];
}

// permute GRU weights: original row g*HG+c -> row 3c+g
__global__ void k_permW(const float* __restrict__ W, const float* __restrict__ bi,
                        float* __restrict__ Wp, float* __restrict__ bp, int K){
    int idx = blockIdx.x*256 + threadIdx.x;
    if (idx < G3*K){
        int row = idx / K, k = idx - row*K;
        int g = row / HG, c = row - g*HG;
        Wp[(3*c+g)*K + k] = W[idx];
    }
    if (idx < G3){
        int g = idx / HG, c = idx - g*HG;
        bp[3*c+g] = bi[idx];
    }
}

// GCN layer1 elementwise (LN-of-affine-in-scalar trick)
__global__ void k_gcn1(const float* __restrict__ g1, const float* __restrict__ bln1,
                       float* __restrict__ H){
    int idx = blockIdx.x*256 + threadIdx.x;
    if (idx >= BT*NNODE*CC) return;
    int row = idx / CC, c = idx - row*CC;
    float y = __ldg(&g_Y[row]);
    float diff = y*g_dWc[c] + g_dbc[c];
    float var = y*y*g_cons[4] + 2.f*y*g_cons[5] + g_cons[6];
    float h = diff*rsqrtf(var + LN_EPS)*g1[c] + bln1[c];
    H[idx] = fmaxf(h, 0.f);
}

// ---------------- GEMMs: 64x96 tile, BK=32, 256 threads, 4x6 per thread, FFMA2 core ----------------
template<bool GUARD>
__global__ __launch_bounds__(256) void k_gemm_nt(const float* __restrict__ A, int lda,
                          const float* __restrict__ B, int ldb,
                          float* __restrict__ C, int ldc,
                          int M, int N, int K, const float* __restrict__ bias){
    __shared__ __align__(16) float As[64][33];
    __shared__ __align__(16) float Bs[32][98];
    int tid = threadIdx.x;
    int tx = tid & 15, ty = tid >> 4;
    int m0 = blockIdx.y*64, n0 = blockIdx.x*96;
    unsigned long long acc[4][3];
#pragma unroll
    for (int i = 0; i < 4; i++)
#pragma unroll
        for (int p = 0; p < 3; p++) acc[i][p] = 0ULL;
    for (int k0 = 0; k0 < K; k0 += 32){
#pragma unroll
        for (int e = tid; e < 2048; e += 256){
            int r = e >> 5, c = e & 31;
            float v;
            if (GUARD) v = (m0+r < M && k0+c < K) ? A[(size_t)(m0+r)*lda + k0+c] : 0.f;
            else       v = A[(size_t)(m0+r)*lda + k0+c];
            As[r][c] = v;
        }
#pragma unroll
        for (int e = tid; e < 3072; e += 256){
            int j = e >> 5, c = e & 31;
            float v;
            if (GUARD) v = (n0+j < N && k0+c < K) ? B[(size_t)(n0+j)*ldb + k0+c] : 0.f;
            else       v = B[(size_t)(n0+j)*ldb + k0+c];
            Bs[c][j] = v;
        }
        __syncthreads();
#pragma unroll
        for (int kk = 0; kk < 32; kk++){
            unsigned long long a2[4], b2[3];
            const unsigned long long* brow = reinterpret_cast<const unsigned long long*>(&Bs[kk][0]);
#pragma unroll
            for (int i = 0; i < 4; i++) a2[i] = pack2dup(As[ty*4+i][kk]);
#pragma unroll
            for (int p = 0; p < 3; p++) b2[p] = brow[tx*3+p];
#pragma unroll
            for (int i = 0; i < 4; i++)
#pragma unroll
                for (int p = 0; p < 3; p++) fma2(acc[i][p], a2[i], b2[p]);
        }
        __syncthreads();
    }
#pragma unroll
    for (int i = 0; i < 4; i++){
        int gr = m0 + ty*4 + i;
        if (GUARD && gr >= M) continue;
        float v[6];
#pragma unroll
        for (int p = 0; p < 3; p++) unpack2(acc[i][p], v[2*p], v[2*p+1]);
#pragma unroll
        for (int j = 0; j < 6; j++){
            int gc = n0 + tx*6 + j;
            if (GUARD && gc >= N) continue;
            float w = v[j];
            if (bias) w += bias[gc];
            C[(size_t)gr*ldc + gc] = w;
        }
    }
}

template<bool GUARD>
__global__ __launch_bounds__(256) void k_gemm_nn(const float* __restrict__ A, int lda,
                          const float* __restrict__ Bbase, int ldb, int bstride,
                          float* __restrict__ Cbase, int ldc, int cstride,
                          int M, int N, int K){
    const float* B = Bbase + (size_t)blockIdx.z*bstride;
    float* C = Cbase + (size_t)blockIdx.z*cstride;
    __shared__ __align__(16) float As[64][33];
    __shared__ __align__(16) float Bs[32][98];
    int tid = threadIdx.x;
    int tx = tid & 15, ty = tid >> 4;
    int m0 = blockIdx.y*64, n0 = blockIdx.x*96;
    unsigned long long acc[4][3];
#pragma unroll
    for (int i = 0; i < 4; i++)
#pragma unroll
        for (int p = 0; p < 3; p++) acc[i][p] = 0ULL;
    for (int k0 = 0; k0 < K; k0 += 32){
#pragma unroll
        for (int e = tid; e < 2048; e += 256){
            int r = e >> 5, c = e & 31;
            float v;
            if (GUARD) v = (m0+r < M && k0+c < K) ? A[(size_t)(m0+r)*lda + k0+c] : 0.f;
            else       v = A[(size_t)(m0+r)*lda + k0+c];
            As[r][c] = v;
        }
#pragma unroll
        for (int e = tid; e < 3072; e += 256){
            int kk = e / 96, j = e - kk*96;
            float v;
            if (GUARD) v = (k0+kk < K && n0+j < N) ? B[(size_t)(k0+kk)*ldb + n0+j] : 0.f;
            else       v = B[(size_t)(k0+kk)*ldb + n0+j];
            Bs[kk][j] = v;
        }
        __syncthreads();
#pragma unroll
        for (int kk = 0; kk < 32; kk++){
            unsigned long long a2[4], b2[3];
            const unsigned long long* brow = reinterpret_cast<const unsigned long long*>(&Bs[kk][0]);
#pragma unroll
            for (int i = 0; i < 4; i++) a2[i] = pack2dup(As[ty*4+i][kk]);
#pragma unroll
            for (int p = 0; p < 3; p++) b2[p] = brow[tx*3+p];
#pragma unroll
            for (int i = 0; i < 4; i++)
#pragma unroll
                for (int p = 0; p < 3; p++) fma2(acc[i][p], a2[i], b2[p]);
        }
        __syncthreads();
    }
#pragma unroll
    for (int i = 0; i < 4; i++){
        int gr = m0 + ty*4 + i;
        if (GUARD && gr >= M) continue;
        float v[6];
#pragma unroll
        for (int p = 0; p < 3; p++) unpack2(acc[i][p], v[2*p], v[2*p+1]);
#pragma unroll
        for (int j = 0; j < 6; j++){
            int gc = n0 + tx*6 + j;
            if (GUARD && gc >= N) continue;
            C[(size_t)gr*ldc + gc] = v[j];
        }
    }
}

// Z @ W2 + b2 -> LN(ln2) -> write in natural (b,t,n,c) order (raw-view reshape semantics)
__global__ __launch_bounds__(256) void k_gemm_nn_ln(const float* __restrict__ A,   // Z, lda=96
                             const float* __restrict__ W2,  // 96x96
                             const float* __restrict__ b2,
                             const float* __restrict__ g2,
                             const float* __restrict__ bln2,
                             float* __restrict__ HS){
    __shared__ __align__(16) float As[64][33];
    __shared__ __align__(16) float Bs[32][98];
    __shared__ float red[64][17];
    int tid = threadIdx.x;
    int tx = tid & 15, ty = tid >> 4;
    int m0 = blockIdx.y*64;
    unsigned long long acc[4][3];
#pragma unroll
    for (int i = 0; i < 4; i++)
#pragma unroll
        for (int p = 0; p < 3; p++) acc[i][p] = 0ULL;
    for (int k0 = 0; k0 < 96; k0 += 32){
#pragma unroll
        for (int e = tid; e < 2048; e += 256){
            int r = e >> 5, c = e & 31;
            As[r][c] = A[(size_t)(m0+r)*96 + k0+c];
        }
#pragma unroll
        for (int e = tid; e < 3072; e += 256){
            int kk = e / 96, j = e - kk*96;
            Bs[kk][j] = W2[(k0+kk)*96 + j];
        }
        __syncthreads();
#pragma unroll
        for (int kk = 0; kk < 32; kk++){
            unsigned long long a2[4], b2[3];
            const unsigned long long* brow = reinterpret_cast<const unsigned long long*>(&Bs[kk][0]);
#pragma unroll
            for (int i = 0; i < 4; i++) a2[i] = pack2dup(As[ty*4+i][kk]);
#pragma unroll
            for (int p = 0; p < 3; p++) b2[p] = brow[tx*3+p];
#pragma unroll
            for (int i = 0; i < 4; i++)
#pragma unroll
                for (int p = 0; p < 3; p++) fma2(acc[i][p], a2[i], b2[p]);
        }
        __syncthreads();
    }
    float v[4][6];
#pragma unroll
    for (int i = 0; i < 4; i++){
#pragma unroll
        for (int p = 0; p < 3; p++) unpack2(acc[i][p], v[i][2*p], v[i][2*p+1]);
#pragma unroll
        for (int j = 0; j < 6; j++) v[i][j] += b2[tx*6+j];
    }
#pragma unroll
    for (int i = 0; i < 4; i++){
        float p = 0.f;
#pragma unroll
        for (int j = 0; j < 6; j++) p += v[i][j];
        red[ty*4+i][tx] = p;
    }
    __syncthreads();
    float mean[4];
#pragma unroll
    for (int i = 0; i < 4; i++){
        float s = 0.f;
#pragma unroll
        for (int q = 0; q < 16; q++) s += red[ty*4+i][q];
        mean[i] = s * (1.0f/96.0f);
    }
    __syncthreads();
#pragma unroll
    for (int i = 0; i < 4; i++){
        float p = 0.f;
#pragma unroll
        for (int j = 0; j < 6; j++){ float d = v[i][j]-mean[i]; p += d*d; }
        red[ty*4+i][tx] = p;
    }
    __syncthreads();
#pragma unroll
    for (int i = 0; i < 4; i++){
        float s = 0.f;
#pragma unroll
        for (int q = 0; q < 16; q++) s += red[ty*4+i][q];
        float rstd = rsqrtf(s*(1.0f/96.0f) + LN_EPS);
        int R = m0 + ty*4 + i;
        size_t base = (size_t)R*96;         // RAW VIEW: identity layout
#pragma unroll
        for (int j = 0; j < 6; j++){
            int col = tx*6 + j;
            HS[base + col] = (v[i][j]-mean[i])*rstd*g2[col] + bln2[col];
        }
    }
}

// GRU recurrent step: hp = h_prev @ Whhp^T (+bhh in epilogue), fused gates.
__global__ __launch_bounds__(256) void k_gru_step(const float* __restrict__ A, int lda,
                           const float* __restrict__ B,      // Whhp 576x192
                           const float* __restrict__ xp,     // + t*576, row stride 6912
                           const float* __restrict__ bhh,    // permuted
                           float* __restrict__ ys){          // + t*192, row stride 2304
    __shared__ __align__(16) float As[64][33];
    __shared__ __align__(16) float Bs[32][98];
    int tid = threadIdx.x;
    int tx = tid & 15, ty = tid >> 4;
    int m0 = blockIdx.y*64, n0 = blockIdx.x*96;
    unsigned long long acc[4][3];
#pragma unroll
    for (int i = 0; i < 4; i++)
#pragma unroll
        for (int p = 0; p < 3; p++) acc[i][p] = 0ULL;
    for (int k0 = 0; k0 < 192; k0 += 32){
#pragma unroll
        for (int e = tid; e < 2048; e += 256){
            int r = e >> 5, c = e & 31;
            As[r][c] = A[(size_t)(m0+r)*lda + k0+c];
        }
#pragma unroll
        for (int e = tid; e < 3072; e += 256){
            int j = e >> 5, c = e & 31;
            Bs[c][j] = B[(size_t)(n0+j)*192 + k0+c];
        }
        __syncthreads();
#pragma unroll
        for (int kk = 0; kk < 32; kk++){
            unsigned long long a2[4], b2[3];
            const unsigned long long* brow = reinterpret_cast<const unsigned long long*>(&Bs[kk][0]);
#pragma unroll
            for (int i = 0; i < 4; i++) a2[i] = pack2dup(As[ty*4+i][kk]);
#pragma unroll
            for (int p = 0; p < 3; p++) b2[p] = brow[tx*3+p];
#pragma unroll
            for (int i = 0; i < 4; i++)
#pragma unroll
                for (int p = 0; p < 3; p++) fma2(acc[i][p], a2[i], b2[p]);
        }
        __syncthreads();
    }
    int j0 = n0 + tx*6;
    int c0 = j0 / 3;
#pragma unroll
    for (int i = 0; i < 4; i++){
        int row = m0 + ty*4 + i;
        const float* xr = xp + (size_t)row*6912;
        float v[6];
#pragma unroll
        for (int p = 0; p < 3; p++) unpack2(acc[i][p], v[2*p], v[2*p+1]);
#pragma unroll
        for (int p = 0; p < 2; p++){
            int j = j0 + p*3;
            int c = c0 + p;
            float hprev = A[(size_t)row*lda + c];   // lda=0 -> g_zero[c]=0 at t=0
            float r = sigf(xr[j]   + v[p*3]   + bhh[j]);
            float z = sigf(xr[j+1] + v[p*3+1] + bhh[j+1]);
            float nn = tanhf(xr[j+2] + r*(v[p*3+2] + bhh[j+2]));
            ys[(size_t)row*2304 + c] = (1.f-z)*nn + z*hprev;
        }
    }
}

// Attention pooling + FC head
__global__ void k_pool(const float* __restrict__ ys, const float* __restrict__ attw,
                       const float* __restrict__ fc1b, const float* __restrict__ fc2b,
                       float* __restrict__ out){
    __shared__ float sOut[12][193];
    __shared__ float sAtt[12];
    __shared__ float sCtx[192];
    __shared__ float sHfc[192];
    __shared__ float red2[16][12];
    int bn = blockIdx.x, tid = threadIdx.x;  // 192 threads
#pragma unroll
    for (int t = 0; t < 12; t++) sOut[t][tid] = ys[(size_t)bn*2304 + t*192 + tid];
    __syncthreads();
    int w = tid >> 5, l = tid & 31;
#pragma unroll
    for (int q = 0; q < 2; q++){
        int t = 2*w + q;
        float p = 0.f;
#pragma unroll
        for (int s = 0; s < 6; s++) p += sOut[t][l + 32*s]*attw[l + 32*s];
#pragma unroll
        for (int s = 16; s > 0; s >>= 1) p += __shfl_down_sync(0xffffffffu, p, s);
        if (l == 0) sAtt[t] = p;
    }
    __syncthreads();
    if (tid == 0){
        float mx = -1e30f;
        for (int t = 0; t < 12; t++) mx = fmaxf(mx, sAtt[t]);
        float s = 0.f;
        for (int t = 0; t < 12; t++){ sAtt[t] = expf(sAtt[t]-mx); s += sAtt[t]; }
        float inv = 1.f/s;
        for (int t = 0; t < 12; t++) sAtt[t] *= inv;
    }
    __syncthreads();
    float c = 0.f;
#pragma unroll
    for (int t = 0; t < 12; t++) c += sAtt[t]*sOut[t][tid];
    sCtx[tid] = c;
    __syncthreads();
    float a = fc1b[tid];
    for (int k = 0; k < 192; k++) a += sCtx[k]*g_fc1t[k*192 + tid];
    sHfc[tid] = gelu_t(a);
    __syncthreads();
    int o = tid % 12, grp = tid / 12;
    float p2 = 0.f;
    for (int j = grp; j < 192; j += 16) p2 += sHfc[j]*g_fc2t[j*12 + o];
    red2[grp][o] = p2;
    __syncthreads();
    if (tid < 12){
        float s = fc2b[tid];
#pragma unroll
        for (int q = 0; q < 16; q++) s += red2[q][tid];
        int b = bn / 1000, n = bn - b*1000;
        out[(size_t)(b*12 + tid)*1000 + n] = s;
    }
}

// ---------------- host launcher ----------------
extern "C" void kernel_launch(void* const* d_in, const int* in_sizes, int n_in,
                              void* d_out, int out_size){
    const float* x      = (const float*)d_in[0];
    const float* A      = (const float*)d_in[1];
    const float* FSP    = (const float*)d_in[2];
    const float* DSP    = (const float*)d_in[3];
    const float* E1     = (const float*)d_in[4];
    const float* E2     = (const float*)d_in[5];
    const float* fus_W  = (const float*)d_in[6];
    const float* fus_b  = (const float*)d_in[7];
    const float* fus_v  = (const float*)d_in[8];
    const float* beta1  = (const float*)d_in[9];
    const float* beta2  = (const float*)d_in[10];
    const float* gcn_W1 = (const float*)d_in[11];
    const float* gcn_b1 = (const float*)d_in[12];
    const float* ln1_g  = (const float*)d_in[13];
    const float* ln1_b  = (const float*)d_in[14];
    const float* gcn_W2 = (const float*)d_in[15];
    const float* gcn_b2 = (const float*)d_in[16];
    const float* ln2_g  = (const float*)d_in[17];
    const float* ln2_b  = (const float*)d_in[18];
    const float* Wih0   = (const float*)d_in[19];
    const float* Whh0   = (const float*)d_in[20];
    const float* bih0   = (const float*)d_in[21];
    const float* bhh0   = (const float*)d_in[22];
    const float* Wih1   = (const float*)d_in[23];
    const float* Whh1   = (const float*)d_in[24];
    const float* bih1   = (const float*)d_in[25];
    const float* bhh1   = (const float*)d_in[26];
    const float* att_w  = (const float*)d_in[27];
    const float* fc1_W  = (const float*)d_in[28];
    const float* fc1_b  = (const float*)d_in[29];
    const float* fc2_W  = (const float*)d_in[30];
    const float* fc2_b  = (const float*)d_in[31];
    float* out = (float*)d_out;

    float *p_big, *p_Wt, *p_S, *p_Y, *p_zero;
    float *p_Wih0p, *p_Whh0p, *p_Wih1p, *p_Whh1p, *p_bih0p, *p_bhh0p, *p_bih1p, *p_bhh1p;
    float *p_fc1t, *p_fc2t;
    cudaGetSymbolAddress((void**)&p_big, g_big);
    cudaGetSymbolAddress((void**)&p_Wt, g_Wt);
    cudaGetSymbolAddress((void**)&p_S, g_S);
    cudaGetSymbolAddress((void**)&p_Y, g_Y);
    cudaGetSymbolAddress((void**)&p_zero, g_zero);
    cudaGetSymbolAddress((void**)&p_Wih0p, g_Wih0p);
    cudaGetSymbolAddress((void**)&p_Whh0p, g_Whh0p);
    cudaGetSymbolAddress((void**)&p_Wih1p, g_Wih1p);
    cudaGetSymbolAddress((void**)&p_Whh1p, g_Whh1p);
    cudaGetSymbolAddress((void**)&p_bih0p, g_bih0p);
    cudaGetSymbolAddress((void**)&p_bhh0p, g_bhh0p);
    cudaGetSymbolAddress((void**)&p_bih1p, g_bih1p);
    cudaGetSymbolAddress((void**)&p_bhh1p, g_bhh1p);
    cudaGetSymbolAddress((void**)&p_fc1t, g_fc1t);
    cudaGetSymbolAddress((void**)&p_fc2t, g_fc2t);

    float* p_HS  = p_big + OFF_HS;
    float* p_XP  = p_big + OFF_XP;
    float* p_H   = p_big + OFF_H;
    float* p_Z   = p_big + OFF_Z;
    float* p_ys0 = p_big + OFF_YS0;
    float* p_ys1 = p_big + OFF_YS1;

    // graph construction
    k_transp<<<(DA*NNODE+255)/256, 256>>>(fus_W, p_Wt, DA, NNODE);
    k_rowsums<<<NNODE, 256>>>(A, FSP, DSP);
    k_adapt<<<NNODE, 256>>>(E1, E2);
    k_proj<<<NNODE, 128>>>(A, FSP, DSP);
    k_scorepart<<<NNODE, 32>>>(fus_b, fus_v, beta1, beta2);
    k_finalize<<<1, 1024>>>(beta1, beta2, gcn_W1, gcn_b1);
    k_shat<<<(NNODE*NNODE+255)/256, 256>>>(A, FSP, DSP);

    // weight prep
    k_permW<<<(G3*CC+255)/256, 256>>>(Wih0, bih0, p_Wih0p, p_bih0p, CC);
    k_permW<<<(G3*HG+255)/256, 256>>>(Whh0, bhh0, p_Whh0p, p_bhh0p, HG);
    k_permW<<<(G3*HG+255)/256, 256>>>(Wih1, bih1, p_Wih1p, p_bih1p, HG);
    k_permW<<<(G3*HG+255)/256, 256>>>(Whh1, bhh1, p_Whh1p, p_bhh1p, HG);
    k_transp<<<(HG*HG+255)/256, 256>>>(fc1_W, p_fc1t, HG, HG);
    k_transp<<<(HOR*HG+255)/256, 256>>>(fc2_W, p_fc2t, HOR, HG);

    // GCN
    {   dim3 g((NNODE+95)/96, (BT+63)/64);
        k_gemm_nt<true><<<g, 256>>>(x, NNODE, p_S, NNODE, p_Y, NNODE, BT, NNODE, NNODE, nullptr);
    }
    k_gcn1<<<(BT*NNODE*CC+255)/256, 256>>>(ln1_g, ln1_b, p_H);
    {   dim3 g(1, (NNODE+63)/64, BT);
        k_gemm_nn<true><<<g, 256>>>(p_S, NNODE, p_H, CC, NNODE*CC, p_Z, CC, NNODE*CC, NNODE, CC, NNODE);
    }
    {   dim3 g(1, (BT*NNODE)/64);
        k_gemm_nn_ln<<<g, 256>>>(p_Z, gcn_W2, gcn_b2, ln2_g, ln2_b, p_HS);
    }

    // GRU layer 0
    {   dim3 g(G3/96, (BNR*TT)/64);
        k_gemm_nt<false><<<g, 256>>>(p_HS, CC, p_Wih0p, CC, p_XP, G3, BNR*TT, G3, CC, p_bih0p);
    }
    for (int t = 0; t < TT; t++){
        const float* hA = (t == 0) ? p_zero : (p_ys0 + (size_t)(t-1)*HG);
        int lda = (t == 0) ? 0 : TT*HG;
        dim3 g(G3/96, BNR/64);
        k_gru_step<<<g, 256>>>(hA, lda, p_Whh0p, p_XP + (size_t)t*G3, p_bhh0p, p_ys0 + (size_t)t*HG);
    }
    // GRU layer 1
    {   dim3 g(G3/96, (BNR*TT)/64);
        k_gemm_nt<false><<<g, 256>>>(p_ys0, HG, p_Wih1p, HG, p_XP, G3, BNR*TT, G3, HG, p_bih1p);
    }
    for (int t = 0; t < TT; t++){
        const float* hA = (t == 0) ? p_zero : (p_ys1 + (size_t)(t-1)*HG);
        int lda = (t == 0) ? 0 : TT*HG;
        dim3 g(G3/96, BNR/64);
        k_gru_step<<<g, 256>>>(hA, lda, p_Whh1p, p_XP + (size_t)t*G3, p_bhh1p, p_ys1 + (size_t)t*HG);
    }

    // pooling + head
    k_pool<<<BNR, 192>>>(p_ys1, att_w, fc1_b, fc2_b, out);
}

// round 15
// speedup vs baseline: 1.3776x; 1.0023x over previous
#include <cuda_runtime.h>
#include <math.h>

#define NNODE 1000
#define TT 12
#define BB 32
#define BT 384
#define CC 96
#define HG 192
#define G3 576
#define BNR 32000
#define DA 32
#define DE 10
#define HOR 12
#define LN_EPS 1e-5f

// ---------------- consolidated big scratch (offsets in floats) ----------------
#define OFF_HS  ((size_t)0)
#define OFF_H   ((size_t)36864000)
#define OFF_Z   ((size_t)73728000)
#define OFF_YS0 ((size_t)110592000)
#define OFF_YS1 ((size_t)184320000)
#define BIG_FLOATS ((size_t)258048000)
__device__ float g_big[BIG_FLOATS];

__device__ float g_Aadp[NNODE*NNODE];
__device__ float g_S[NNODE*NNODE];
__device__ float g_rs[3*NNODE];
__device__ float g_Wt[NNODE*DA];
__device__ float g_P[4*NNODE*DA];
__device__ float g_scpart[3*NNODE];
__device__ float g_cons[8];
__device__ float g_dWc[CC];
__device__ float g_dbc[CC];
__device__ float g_dinv[NNODE];
__device__ float g_Y[BT*NNODE];
__device__ float g_zero[HG];            // never written: GRU h0
__device__ float g_Wc0[G3*(HG+CC)];     // [Whh0p | Wih0p], 576 x 288
__device__ float g_Wc1[G3*(HG+HG)];     // [Whh1p | Wih1p], 576 x 384
__device__ float g_bih0p[G3];
__device__ float g_bhh0p[G3];
__device__ float g_bih1p[G3];
__device__ float g_bhh1p[G3];
__device__ float g_fc1t[HG*HG];
__device__ float g_fc2t[HG*HOR];

__device__ __forceinline__ float sigf(float x){ return 1.0f/(1.0f+expf(-x)); }
__device__ __forceinline__ float gelu_t(float x){
    float x3 = x*x*x;
    return 0.5f*x*(1.0f + tanhf(0.7978845608028654f*(x + 0.044715f*x3)));
}

// ---------------- packed f32x2 helpers (sm_103a FFMA2) ----------------
__device__ __forceinline__ unsigned long long pack2dup(float a){
    unsigned long long r;
    asm("mov.b64 %0, {%1, %1};" : "=l"(r) : "f"(a));
    return r;
}
__device__ __forceinline__ void fma2(unsigned long long& d, unsigned long long a, unsigned long long b){
    asm("fma.rn.f32x2 %0, %1, %2, %0;" : "+l"(d) : "l"(a), "l"(b));
}
__device__ __forceinline__ void unpack2(unsigned long long v, float& lo, float& hi){
    asm("mov.b64 {%0, %1}, %2;" : "=f"(lo), "=f"(hi) : "l"(v));
}

// ---------------- prep ----------------
__global__ void k_transp(const float* __restrict__ src, float* __restrict__ dst, int R, int C){
    int i = blockIdx.x*256 + threadIdx.x;
    if (i < R*C){ int r = i / C, c = i % C; dst[c*R + r] = src[i]; }
}

__global__ void k_rowsums(const float* __restrict__ A, const float* __restrict__ F, const float* __restrict__ D){
    __shared__ float red[256];
    int n = blockIdx.x, tid = threadIdx.x;
    float s[3] = {0.f,0.f,0.f};
    for (int m = tid; m < NNODE; m += 256){
        s[0] += A[n*NNODE+m]; s[1] += F[n*NNODE+m]; s[2] += D[n*NNODE+m];
    }
    for (int k = 0; k < 3; k++){
        red[tid] = s[k]; __syncthreads();
        for (int st = 128; st > 0; st >>= 1){ if (tid < st) red[tid] += red[tid+st]; __syncthreads(); }
        if (tid == 0) g_rs[k*NNODE+n] = red[0];
        __syncthreads();
    }
}

__global__ void k_adapt(const float* __restrict__ E1, const float* __restrict__ E2){
    __shared__ float e[NNODE];
    __shared__ float red[256];
    int n = blockIdx.x, tid = threadIdx.x;
    float e1[DE];
#pragma unroll
    for (int d = 0; d < DE; d++) e1[d] = E1[n*DE + d];
    float lmax = -1e30f;
    for (int m = tid; m < NNODE; m += 256){
        float dot = 0.f;
#pragma unroll
        for (int d = 0; d < DE; d++) dot += e1[d]*E2[m*DE + d];
        dot = fmaxf(dot, 0.f);
        e[m] = dot; lmax = fmaxf(lmax, dot);
    }
    red[tid] = lmax; __syncthreads();
    for (int st = 128; st > 0; st >>= 1){ if (tid < st) red[tid] = fmaxf(red[tid], red[tid+st]); __syncthreads(); }
    float mx = red[0]; __syncthreads();
    float ls = 0.f;
    for (int m = tid; m < NNODE; m += 256){ float ex = expf(e[m]-mx); e[m] = ex; ls += ex; }
    red[tid] = ls; __syncthreads();
    for (int st = 128; st > 0; st >>= 1){ if (tid < st) red[tid] += red[tid+st]; __syncthreads(); }
    float inv = 1.0f/red[0];
    for (int m = tid; m < NNODE; m += 256) g_Aadp[n*NNODE+m] = e[m]*inv;
}

__global__ void k_proj(const float* __restrict__ A, const float* __restrict__ F, const float* __restrict__ D){
    __shared__ float r[4][NNODE];
    int n = blockIdx.x, tid = threadIdx.x;  // 128 threads
    for (int m = tid; m < NNODE; m += 128){
        r[0][m] = A[n*NNODE+m]; r[1][m] = F[n*NNODE+m]; r[2][m] = D[n*NNODE+m]; r[3][m] = g_Aadp[n*NNODE+m];
    }
    __syncthreads();
    int w = tid >> 5, a = tid & 31;
    float acc = 0.f;
    for (int m = 0; m < NNODE; m++) acc += r[w][m]*g_Wt[m*DA + a];
    g_P[w*(NNODE*DA) + n*DA + a] = acc;
}

__global__ void k_scorepart(const float* __restrict__ fus_b, const float* __restrict__ fus_v,
                            const float* __restrict__ beta1, const float* __restrict__ beta2){
    int n = blockIdx.x, a = threadIdx.x; // 32 threads
    float w1 = sigf(beta1[0]), w2 = sigf(beta2[0]);
    float pA = g_P[0*NNODE*DA + n*DA + a];
    float pF = g_P[1*NNODE*DA + n*DA + a];
    float pD = g_P[2*NNODE*DA + n*DA + a];
    float pP = g_P[3*NNODE*DA + n*DA + a];
    float fb = fus_b[a], fv = fus_v[a];
    float t0 = tanhf(0.5f*pA + 0.5f*pP + fb)*fv;
    float t1 = tanhf(w1*pA + (1.f-w1)*pF + fb)*fv;
    float t2 = tanhf(w2*pA + (1.f-w2)*pD + fb)*fv;
#pragma unroll
    for (int s = 16; s > 0; s >>= 1){
        t0 += __shfl_down_sync(0xffffffffu, t0, s);
        t1 += __shfl_down_sync(0xffffffffu, t1, s);
        t2 += __shfl_down_sync(0xffffffffu, t2, s);
    }
    if (a == 0){ g_scpart[0*NNODE+n]=t0; g_scpart[1*NNODE+n]=t1; g_scpart[2*NNODE+n]=t2; }
}

__global__ void k_finalize(const float* __restrict__ beta1, const float* __restrict__ beta2,
                           const float* __restrict__ W1, const float* __restrict__ b1){
    __shared__ float red[1024];
    __shared__ float sc[3];
    __shared__ float st[6];
    int tid = threadIdx.x;
    for (int k = 0; k < 3; k++){
        red[tid] = (tid < NNODE) ? g_scpart[k*NNODE + tid] : 0.f;
        __syncthreads();
        for (int s = 512; s > 0; s >>= 1){ if (tid < s) red[tid] += red[tid+s]; __syncthreads(); }
        if (tid == 0) sc[k] = red[0] / (float)NNODE;
        __syncthreads();
    }
    red[tid] = (tid < CC) ? W1[tid] : 0.f; __syncthreads();
    for (int s = 512; s > 0; s >>= 1){ if (tid < s) red[tid] += red[tid+s]; __syncthreads(); }
    if (tid == 0) st[0] = red[0]/(float)CC;
    __syncthreads();
    red[tid] = (tid < CC) ? b1[tid] : 0.f; __syncthreads();
    for (int s = 512; s > 0; s >>= 1){ if (tid < s) red[tid] += red[tid+s]; __syncthreads(); }
    if (tid == 0) st[1] = red[0]/(float)CC;
    __syncthreads();
    float dw = 0.f, db = 0.f;
    if (tid < CC){
        dw = W1[tid] - st[0]; db = b1[tid] - st[1];
        g_dWc[tid] = dw; g_dbc[tid] = db;
    }
    red[tid] = dw*dw; __syncthreads();
    for (int s = 512; s > 0; s >>= 1){ if (tid < s) red[tid] += red[tid+s]; __syncthreads(); }
    if (tid == 0) st[2] = red[0]/(float)CC;
    __syncthreads();
    red[tid] = dw*db; __syncthreads();
    for (int s = 512; s > 0; s >>= 1){ if (tid < s) red[tid] += red[tid+s]; __syncthreads(); }
    if (tid == 0) st[3] = red[0]/(float)CC;
    __syncthreads();
    red[tid] = db*db; __syncthreads();
    for (int s = 512; s > 0; s >>= 1){ if (tid < s) red[tid] += red[tid+s]; __syncthreads(); }
    if (tid == 0) st[4] = red[0]/(float)CC;
    __syncthreads();
    if (tid == 0){
        float w1 = sigf(beta1[0]), w2 = sigf(beta2[0]);
        float m = fmaxf(sc[0], fmaxf(sc[1], sc[2]));
        float e0 = expf(sc[0]-m), e1 = expf(sc[1]-m), e2 = expf(sc[2]-m);
        float is = 1.f/(e0+e1+e2);
        float a0 = e0*is, a1 = e1*is, a2 = e2*is;
        g_cons[0] = 0.5f*a0 + w1*a1 + w2*a2;
        g_cons[1] = a1*(1.f-w1);
        g_cons[2] = a2*(1.f-w2);
        g_cons[3] = 0.5f*a0;
        g_cons[4] = st[2];
        g_cons[5] = st[3];
        g_cons[6] = st[4];
    }
    __syncthreads();
    if (tid < NNODE){
        float d = g_cons[0]*g_rs[tid] + g_cons[1]*g_rs[NNODE+tid] + g_cons[2]*g_rs[2*NNODE+tid] + g_cons[3] + 1.0f;
        g_dinv[tid] = rsqrtf(fmaxf(d, 1e-12f));
    }
}

__global__ void k_shat(const float* __restrict__ A, const float* __restrict__ F, const float* __restrict__ D){
    int idx = blockIdx.x*256 + threadIdx.x;
    if (idx >= NNODE*NNODE) return;
    int n = idx / NNODE, m = idx - n*NNODE;
    float v = g_cons[0]*A[idx] + g_cons[1]*F[idx] + g_cons[2]*D[idx] + g_cons[3]*g_Aadp[idx];
    if (n == m) v += 1.0f;
    g_S[idx] = v * g_dinv[n]*g_dinv[m];
}

// permute GRU weight rows (g*HG+c -> 3c+g) into combined matrix at column offset
__global__ void k_permW2(const float* __restrict__ W, float* __restrict__ Wp,
                         int K, int dstStride, int colOff){
    int idx = blockIdx.x*256 + threadIdx.x;
    if (idx < G3*K){
        int row = idx / K, k = idx - row*K;
        int g = row / HG, c = row - g*HG;
        Wp[(size_t)(3*c+g)*dstStride + colOff + k] = W[idx];
    }
}

__global__ void k_permB(const float* __restrict__ b0, const float* __restrict__ b1,
                        const float* __restrict__ b2, const float* __restrict__ b3,
                        float* __restrict__ p0, float* __restrict__ p1,
                        float* __restrict__ p2, float* __restrict__ p3){
    int idx = blockIdx.x*256 + threadIdx.x;
    if (idx < G3){
        int g = idx / HG, c = idx - g*HG;
        int d = 3*c+g;
        p0[d] = b0[idx]; p1[d] = b1[idx]; p2[d] = b2[idx]; p3[d] = b3[idx];
    }
}

// GCN layer1 elementwise (LN-of-affine-in-scalar trick)
__global__ void k_gcn1(const float* __restrict__ g1, const float* __restrict__ bln1,
                       float* __restrict__ H){
    int idx = blockIdx.x*256 + threadIdx.x;
    if (idx >= BT*NNODE*CC) return;
    int row = idx / CC, c = idx - row*CC;
    float y = __ldg(&g_Y[row]);
    float diff = y*g_dWc[c] + g_dbc[c];
    float var = y*y*g_cons[4] + 2.f*y*g_cons[5] + g_cons[6];
    float h = diff*rsqrtf(var + LN_EPS)*g1[c] + bln1[c];
    H[idx] = fmaxf(h, 0.f);
}

// ---------------- GEMMs: 64x96 tile, BK=32, 256 threads, 4x6 per thread, FFMA2 core ----------------
template<bool GUARD>
__global__ __launch_bounds__(256) void k_gemm_nt(const float* __restrict__ A, int lda,
                          const float* __restrict__ B, int ldb,
                          float* __restrict__ C, int ldc,
                          int M, int N, int K, const float* __restrict__ bias){
    __shared__ __align__(16) float As[64][33];
    __shared__ __align__(16) float Bs[32][98];
    int tid = threadIdx.x;
    int tx = tid & 15, ty = tid >> 4;
    int m0 = blockIdx.y*64, n0 = blockIdx.x*96;
    unsigned long long acc[4][3];
#pragma unroll
    for (int i = 0; i < 4; i++)
#pragma unroll
        for (int p = 0; p < 3; p++) acc[i][p] = 0ULL;
    for (int k0 = 0; k0 < K; k0 += 32){
#pragma unroll
        for (int e = tid; e < 2048; e += 256){
            int r = e >> 5, c = e & 31;
            float v;
            if (GUARD) v = (m0+r < M && k0+c < K) ? A[(size_t)(m0+r)*lda + k0+c] : 0.f;
            else       v = A[(size_t)(m0+r)*lda + k0+c];
            As[r][c] = v;
        }
#pragma unroll
        for (int e = tid; e < 3072; e += 256){
            int j = e >> 5, c = e & 31;
            float v;
            if (GUARD) v = (n0+j < N && k0+c < K) ? B[(size_t)(n0+j)*ldb + k0+c] : 0.f;
            else       v = B[(size_t)(n0+j)*ldb + k0+c];
            Bs[c][j] = v;
        }
        __syncthreads();
#pragma unroll
        for (int kk = 0; kk < 32; kk++){
            unsigned long long a2[4], b2[3];
            const unsigned long long* brow = reinterpret_cast<const unsigned long long*>(&Bs[kk][0]);
#pragma unroll
            for (int i = 0; i < 4; i++) a2[i] = pack2dup(As[ty*4+i][kk]);
#pragma unroll
            for (int p = 0; p < 3; p++) b2[p] = brow[tx*3+p];
#pragma unroll
            for (int i = 0; i < 4; i++)
#pragma unroll
                for (int p = 0; p < 3; p++) fma2(acc[i][p], a2[i], b2[p]);
        }
        __syncthreads();
    }
#pragma unroll
    for (int i = 0; i < 4; i++){
        int gr = m0 + ty*4 + i;
        if (GUARD && gr >= M) continue;
        float v[6];
#pragma unroll
        for (int p = 0; p < 3; p++) unpack2(acc[i][p], v[2*p], v[2*p+1]);
#pragma unroll
        for (int j = 0; j < 6; j++){
            int gc = n0 + tx*6 + j;
            if (GUARD && gc >= N) continue;
            float w = v[j];
            if (bias) w += bias[gc];
            C[(size_t)gr*ldc + gc] = w;
        }
    }
}

template<bool GUARD>
__global__ __launch_bounds__(256) void k_gemm_nn(const float* __restrict__ A, int lda,
                          const float* __restrict__ Bbase, int ldb, int bstride,
                          float* __restrict__ Cbase, int ldc, int cstride,
                          int M, int N, int K){
    const float* B = Bbase + (size_t)blockIdx.z*bstride;
    float* C = Cbase + (size_t)blockIdx.z*cstride;
    __shared__ __align__(16) float As[64][33];
    __shared__ __align__(16) float Bs[32][98];
    int tid = threadIdx.x;
    int tx = tid & 15, ty = tid >> 4;
    int m0 = blockIdx.y*64, n0 = blockIdx.x*96;
    unsigned long long acc[4][3];
#pragma unroll
    for (int i = 0; i < 4; i++)
#pragma unroll
        for (int p = 0; p < 3; p++) acc[i][p] = 0ULL;
    for (int k0 = 0; k0 < K; k0 += 32){
#pragma unroll
        for (int e = tid; e < 2048; e += 256){
            int r = e >> 5, c = e & 31;
            float v;
            if (GUARD) v = (m0+r < M && k0+c < K) ? A[(size_t)(m0+r)*lda + k0+c] : 0.f;
            else       v = A[(size_t)(m0+r)*lda + k0+c];
            As[r][c] = v;
        }
#pragma unroll
        for (int e = tid; e < 3072; e += 256){
            int kk = e / 96, j = e - kk*96;
            float v;
            if (GUARD) v = (k0+kk < K && n0+j < N) ? B[(size_t)(k0+kk)*ldb + n0+j] : 0.f;
            else       v = B[(size_t)(k0+kk)*ldb + n0+j];
            Bs[kk][j] = v;
        }
        __syncthreads();
#pragma unroll
        for (int kk = 0; kk < 32; kk++){
            unsigned long long a2[4], b2[3];
            const unsigned long long* brow = reinterpret_cast<const unsigned long long*>(&Bs[kk][0]);
#pragma unroll
            for (int i = 0; i < 4; i++) a2[i] = pack2dup(As[ty*4+i][kk]);
#pragma unroll
            for (int p = 0; p < 3; p++) b2[p] = brow[tx*3+p];
#pragma unroll
            for (int i = 0; i < 4; i++)
#pragma unroll
                for (int p = 0; p < 3; p++) fma2(acc[i][p], a2[i], b2[p]);
        }
        __syncthreads();
    }
#pragma unroll
    for (int i = 0; i < 4; i++){
        int gr = m0 + ty*4 + i;
        if (GUARD && gr >= M) continue;
        float v[6];
#pragma unroll
        for (int p = 0; p < 3; p++) unpack2(acc[i][p], v[2*p], v[2*p+1]);
#pragma unroll
        for (int j = 0; j < 6; j++){
            int gc = n0 + tx*6 + j;
            if (GUARD && gc >= N) continue;
            C[(size_t)gr*ldc + gc] = v[j];
        }
    }
}

// Z @ W2 + b2 -> LN(ln2) -> write in natural (b,t,n,c) order (raw-view reshape semantics)
__global__ __launch_bounds__(256) void k_gemm_nn_ln(const float* __restrict__ A,   // Z, lda=96
                             const float* __restrict__ W2,  // 96x96
                             const float* __restrict__ b2,
                             const float* __restrict__ g2,
                             const float* __restrict__ bln2,
                             float* __restrict__ HS){
    __shared__ __align__(16) float As[64][33];
    __shared__ __align__(16) float Bs[32][98];
    __shared__ float red[64][17];
    int tid = threadIdx.x;
    int tx = tid & 15, ty = tid >> 4;
    int m0 = blockIdx.y*64;
    unsigned long long acc[4][3];
#pragma unroll
    for (int i = 0; i < 4; i++)
#pragma unroll
        for (int p = 0; p < 3; p++) acc[i][p] = 0ULL;
    for (int k0 = 0; k0 < 96; k0 += 32){
#pragma unroll
        for (int e = tid; e < 2048; e += 256){
            int r = e >> 5, c = e & 31;
            As[r][c] = A[(size_t)(m0+r)*96 + k0+c];
        }
#pragma unroll
        for (int e = tid; e < 3072; e += 256){
            int kk = e / 96, j = e - kk*96;
            Bs[kk][j] = W2[(k0+kk)*96 + j];
        }
        __syncthreads();
#pragma unroll
        for (int kk = 0; kk < 32; kk++){
            unsigned long long a2[4], b2[3];
            const unsigned long long* brow = reinterpret_cast<const unsigned long long*>(&Bs[kk][0]);
#pragma unroll
            for (int i = 0; i < 4; i++) a2[i] = pack2dup(As[ty*4+i][kk]);
#pragma unroll
            for (int p = 0; p < 3; p++) b2[p] = brow[tx*3+p];
#pragma unroll
            for (int i = 0; i < 4; i++)
#pragma unroll
                for (int p = 0; p < 3; p++) fma2(acc[i][p], a2[i], b2[p]);
        }
        __syncthreads();
    }
    float v[4][6];
#pragma unroll
    for (int i = 0; i < 4; i++){
#pragma unroll
        for (int p = 0; p < 3; p++) unpack2(acc[i][p], v[i][2*p], v[i][2*p+1]);
#pragma unroll
        for (int j = 0; j < 6; j++) v[i][j] += b2[tx*6+j];
    }
#pragma unroll
    for (int i = 0; i < 4; i++){
        float p = 0.f;
#pragma unroll
        for (int j = 0; j < 6; j++) p += v[i][j];
        red[ty*4+i][tx] = p;
    }
    __syncthreads();
    float mean[4];
#pragma unroll
    for (int i = 0; i < 4; i++){
        float s = 0.f;
#pragma unroll
        for (int q = 0; q < 16; q++) s += red[ty*4+i][q];
        mean[i] = s * (1.0f/96.0f);
    }
    __syncthreads();
#pragma unroll
    for (int i = 0; i < 4; i++){
        float p = 0.f;
#pragma unroll
        for (int j = 0; j < 6; j++){ float d = v[i][j]-mean[i]; p += d*d; }
        red[ty*4+i][tx] = p;
    }
    __syncthreads();
#pragma unroll
    for (int i = 0; i < 4; i++){
        float s = 0.f;
#pragma unroll
        for (int q = 0; q < 16; q++) s += red[ty*4+i][q];
        float rstd = rsqrtf(s*(1.0f/96.0f) + LN_EPS);
        int R = m0 + ty*4 + i;
        size_t base = (size_t)R*96;         // RAW VIEW: identity layout
#pragma unroll
        for (int j = 0; j < 6; j++){
            int col = tx*6 + j;
            HS[base + col] = (v[i][j]-mean[i])*rstd*g2[col] + bln2[col];
        }
    }
}

// Fused GRU step: acc_h = h_prev @ Whhp^T (K=KH), acc_x = x_t @ Wihp^T (K=KX),
// both from combined weight B[576][KH+KX]; full gate math in epilogue.
template<int KH, int KX>
__global__ __launch_bounds__(256) void k_gru_fused(
    const float* __restrict__ Ah, int ldah,      // h_prev rows (lda=0 -> zero buffer)
    const float* __restrict__ Ax, int ldax,      // x_t rows (pre-offset to slice)
    const float* __restrict__ B,                 // combined 576 x (KH+KX)
    const float* __restrict__ bih, const float* __restrict__ bhh,  // permuted
    float* __restrict__ ys){                     // + t*192, row stride 2304
    constexpr int KT = KH + KX;
    __shared__ __align__(16) float As[64][33];
    __shared__ __align__(16) float Bs[32][98];
    int tid = threadIdx.x;
    int tx = tid & 15, ty = tid >> 4;
    int m0 = blockIdx.y*64, n0 = blockIdx.x*96;
    unsigned long long ah[4][3], ax[4][3];
#pragma unroll
    for (int i = 0; i < 4; i++)
#pragma unroll
        for (int p = 0; p < 3; p++){ ah[i][p] = 0ULL; ax[i][p] = 0ULL; }

    // ---- h chunks ----
#pragma unroll
    for (int k0 = 0; k0 < KH; k0 += 32){
#pragma unroll
        for (int e = tid; e < 2048; e += 256){
            int r = e >> 5, c = e & 31;
            As[r][c] = Ah[(size_t)(m0+r)*ldah + k0+c];
        }
#pragma unroll
        for (int e = tid; e < 3072; e += 256){
            int j = e >> 5, c = e & 31;
            Bs[c][j] = B[(size_t)(n0+j)*KT + k0+c];
        }
        __syncthreads();
#pragma unroll
        for (int kk = 0; kk < 32; kk++){
            unsigned long long a2[4], b2[3];
            const unsigned long long* brow = reinterpret_cast<const unsigned long long*>(&Bs[kk][0]);
#pragma unroll
            for (int i = 0; i < 4; i++) a2[i] = pack2dup(As[ty*4+i][kk]);
#pragma unroll
            for (int p = 0; p < 3; p++) b2[p] = brow[tx*3+p];
#pragma unroll
            for (int i = 0; i < 4; i++)
#pragma unroll
                for (int p = 0; p < 3; p++) fma2(ah[i][p], a2[i], b2[p]);
        }
        __syncthreads();
    }
    // ---- x chunks ----
#pragma unroll
    for (int k0 = 0; k0 < KX; k0 += 32){
#pragma unroll
        for (int e = tid; e < 2048; e += 256){
            int r = e >> 5, c = e & 31;
            As[r][c] = Ax[(size_t)(m0+r)*ldax + k0+c];
        }
#pragma unroll
        for (int e = tid; e < 3072; e += 256){
            int j = e >> 5, c = e & 31;
            Bs[c][j] = B[(size_t)(n0+j)*KT + KH + k0+c];
        }
        __syncthreads();
#pragma unroll
        for (int kk = 0; kk < 32; kk++){
            unsigned long long a2[4], b2[3];
            const unsigned long long* brow = reinterpret_cast<const unsigned long long*>(&Bs[kk][0]);
#pragma unroll
            for (int i = 0; i < 4; i++) a2[i] = pack2dup(As[ty*4+i][kk]);
#pragma unroll
            for (int p = 0; p < 3; p++) b2[p] = brow[tx*3+p];
#pragma unroll
            for (int i = 0; i < 4; i++)
#pragma unroll
                for (int p = 0; p < 3; p++) fma2(ax[i][p], a2[i], b2[p]);
        }
        __syncthreads();
    }

    int j0 = n0 + tx*6;
    int c0 = j0 / 3;
#pragma unroll
    for (int i = 0; i < 4; i++){
        int row = m0 + ty*4 + i;
        float vh[6], vx[6];
#pragma unroll
        for (int p = 0; p < 3; p++){ unpack2(ah[i][p], vh[2*p], vh[2*p+1]); unpack2(ax[i][p], vx[2*p], vx[2*p+1]); }
#pragma unroll
        for (int p = 0; p < 2; p++){
            int j = j0 + p*3;
            int c = c0 + p;
            float hprev = Ah[(size_t)row*ldah + c];   // lda=0 -> g_zero[c]=0 at t=0
            float r = sigf(vx[p*3]   + bih[j]   + vh[p*3]   + bhh[j]);
            float z = sigf(vx[p*3+1] + bih[j+1] + vh[p*3+1] + bhh[j+1]);
            float nn = tanhf(vx[p*3+2] + bih[j+2] + r*(vh[p*3+2] + bhh[j+2]));
            ys[(size_t)row*2304 + c] = (1.f-z)*nn + z*hprev;
        }
    }
}

// Attention pooling + FC head
__global__ void k_pool(const float* __restrict__ ys, const float* __restrict__ attw,
                       const float* __restrict__ fc1b, const float* __restrict__ fc2b,
                       float* __restrict__ out){
    __shared__ float sOut[12][193];
    __shared__ float sAtt[12];
    __shared__ float sCtx[192];
    __shared__ float sHfc[192];
    __shared__ float red2[16][12];
    int bn = blockIdx.x, tid = threadIdx.x;  // 192 threads
#pragma unroll
    for (int t = 0; t < 12; t++) sOut[t][tid] = ys[(size_t)bn*2304 + t*192 + tid];
    __syncthreads();
    int w = tid >> 5, l = tid & 31;
#pragma unroll
    for (int q = 0; q < 2; q++){
        int t = 2*w + q;
        float p = 0.f;
#pragma unroll
        for (int s = 0; s < 6; s++) p += sOut[t][l + 32*s]*attw[l + 32*s];
#pragma unroll
        for (int s = 16; s > 0; s >>= 1) p += __shfl_down_sync(0xffffffffu, p, s);
        if (l == 0) sAtt[t] = p;
    }
    __syncthreads();
    if (tid == 0){
        float mx = -1e30f;
        for (int t = 0; t < 12; t++) mx = fmaxf(mx, sAtt[t]);
        float s = 0.f;
        for (int t = 0; t < 12; t++){ sAtt[t] = expf(sAtt[t]-mx); s += sAtt[t]; }
        float inv = 1.f/s;
        for (int t = 0; t < 12; t++) sAtt[t] *= inv;
    }
    __syncthreads();
    float c = 0.f;
#pragma unroll
    for (int t = 0; t < 12; t++) c += sAtt[t]*sOut[t][tid];
    sCtx[tid] = c;
    __syncthreads();
    float a0 = 0.f, a1 = 0.f, a2 = 0.f, a3 = 0.f;
#pragma unroll 4
    for (int k = 0; k < 192; k += 4){
        a0 += sCtx[k]  *g_fc1t[(k)*192 + tid];
        a1 += sCtx[k+1]*g_fc1t[(k+1)*192 + tid];
        a2 += sCtx[k+2]*g_fc1t[(k+2)*192 + tid];
        a3 += sCtx[k+3]*g_fc1t[(k+3)*192 + tid];
    }
    sHfc[tid] = gelu_t(fc1b[tid] + ((a0+a1)+(a2+a3)));
    __syncthreads();
    int o = tid % 12, grp = tid / 12;
    float p2 = 0.f;
    for (int j = grp; j < 192; j += 16) p2 += sHfc[j]*g_fc2t[j*12 + o];
    red2[grp][o] = p2;
    __syncthreads();
    if (tid < 12){
        float s = fc2b[tid];
#pragma unroll
        for (int q = 0; q < 16; q++) s += red2[q][tid];
        int b = bn / 1000, n = bn - b*1000;
        out[(size_t)(b*12 + tid)*1000 + n] = s;
    }
}

// ---------------- host launcher ----------------
extern "C" void kernel_launch(void* const* d_in, const int* in_sizes, int n_in,
                              void* d_out, int out_size){
    const float* x      = (const float*)d_in[0];
    const float* A      = (const float*)d_in[1];
    const float* FSP    = (const float*)d_in[2];
    const float* DSP    = (const float*)d_in[3];
    const float* E1     = (const float*)d_in[4];
    const float* E2     = (const float*)d_in[5];
    const float* fus_W  = (const float*)d_in[6];
    const float* fus_b  = (const float*)d_in[7];
    const float* fus_v  = (const float*)d_in[8];
    const float* beta1  = (const float*)d_in[9];
    const float* beta2  = (const float*)d_in[10];
    const float* gcn_W1 = (const float*)d_in[11];
    const float* gcn_b1 = (const float*)d_in[12];
    const float* ln1_g  = (const float*)d_in[13];
    const float* ln1_b  = (const float*)d_in[14];
    const float* gcn_W2 = (const float*)d_in[15];
    const float* gcn_b2 = (const float*)d_in[16];
    const float* ln2_g  = (const float*)d_in[17];
    const float* ln2_b  = (const float*)d_in[18];
    const float* Wih0   = (const float*)d_in[19];
    const float* Whh0   = (const float*)d_in[20];
    const float* bih0   = (const float*)d_in[21];
    const float* bhh0   = (const float*)d_in[22];
    const float* Wih1   = (const float*)d_in[23];
    const float* Whh1   = (const float*)d_in[24];
    const float* bih1   = (const float*)d_in[25];
    const float* bhh1   = (const float*)d_in[26];
    const float* att_w  = (const float*)d_in[27];
    const float* fc1_W  = (const float*)d_in[28];
    const float* fc1_b  = (const float*)d_in[29];
    const float* fc2_W  = (const float*)d_in[30];
    const float* fc2_b  = (const float*)d_in[31];
    float* out = (float*)d_out;

    float *p_big, *p_Wt, *p_S, *p_Y, *p_zero, *p_Wc0, *p_Wc1;
    float *p_bih0p, *p_bhh0p, *p_bih1p, *p_bhh1p;
    float *p_fc1t, *p_fc2t;
    cudaGetSymbolAddress((void**)&p_big, g_big);
    cudaGetSymbolAddress((void**)&p_Wt, g_Wt);
    cudaGetSymbolAddress((void**)&p_S, g_S);
    cudaGetSymbolAddress((void**)&p_Y, g_Y);
    cudaGetSymbolAddress((void**)&p_zero, g_zero);
    cudaGetSymbolAddress((void**)&p_Wc0, g_Wc0);
    cudaGetSymbolAddress((void**)&p_Wc1, g_Wc1);
    cudaGetSymbolAddress((void**)&p_bih0p, g_bih0p);
    cudaGetSymbolAddress((void**)&p_bhh0p, g_bhh0p);
    cudaGetSymbolAddress((void**)&p_bih1p, g_bih1p);
    cudaGetSymbolAddress((void**)&p_bhh1p, g_bhh1p);
    cudaGetSymbolAddress((void**)&p_fc1t, g_fc1t);
    cudaGetSymbolAddress((void**)&p_fc2t, g_fc2t);

    float* p_HS  = p_big + OFF_HS;
    float* p_H   = p_big + OFF_H;
    float* p_Z   = p_big + OFF_Z;
    float* p_ys0 = p_big + OFF_YS0;
    float* p_ys1 = p_big + OFF_YS1;

    // graph construction
    k_transp<<<(DA*NNODE+255)/256, 256>>>(fus_W, p_Wt, DA, NNODE);
    k_rowsums<<<NNODE, 256>>>(A, FSP, DSP);
    k_adapt<<<NNODE, 256>>>(E1, E2);
    k_proj<<<NNODE, 128>>>(A, FSP, DSP);
    k_scorepart<<<NNODE, 32>>>(fus_b, fus_v, beta1, beta2);
    k_finalize<<<1, 1024>>>(beta1, beta2, gcn_W1, gcn_b1);
    k_shat<<<(NNODE*NNODE+255)/256, 256>>>(A, FSP, DSP);

    // weight prep: combined permuted GRU weights + permuted biases
    k_permW2<<<(G3*HG+255)/256, 256>>>(Whh0, p_Wc0, HG, HG+CC, 0);
    k_permW2<<<(G3*CC+255)/256, 256>>>(Wih0, p_Wc0, CC, HG+CC, HG);
    k_permW2<<<(G3*HG+255)/256, 256>>>(Whh1, p_Wc1, HG, HG+HG, 0);
    k_permW2<<<(G3*HG+255)/256, 256>>>(Wih1, p_Wc1, HG, HG+HG, HG);
    k_permB<<<(G3+255)/256, 256>>>(bih0, bhh0, bih1, bhh1, p_bih0p, p_bhh0p, p_bih1p, p_bhh1p);
    k_transp<<<(HG*HG+255)/256, 256>>>(fc1_W, p_fc1t, HG, HG);
    k_transp<<<(HOR*HG+255)/256, 256>>>(fc2_W, p_fc2t, HOR, HG);

    // GCN
    {   dim3 g((NNODE+95)/96, (BT+63)/64);
        k_gemm_nt<true><<<g, 256>>>(x, NNODE, p_S, NNODE, p_Y, NNODE, BT, NNODE, NNODE, nullptr);
    }
    k_gcn1<<<(BT*NNODE*CC+255)/256, 256>>>(ln1_g, ln1_b, p_H);
    {   dim3 g(1, (NNODE+63)/64, BT);
        k_gemm_nn<true><<<g, 256>>>(p_S, NNODE, p_H, CC, NNODE*CC, p_Z, CC, NNODE*CC, NNODE, CC, NNODE);
    }
    {   dim3 g(1, (BT*NNODE)/64);
        k_gemm_nn_ln<<<g, 256>>>(p_Z, gcn_W2, gcn_b2, ln2_g, ln2_b, p_HS);
    }

    // GRU layer 0 (fused x-projection, KX=96 from HS raw-view rows)
    for (int t = 0; t < TT; t++){
        const float* hA = (t == 0) ? p_zero : (p_ys0 + (size_t)(t-1)*HG);
        int ldah = (t == 0) ? 0 : TT*HG;
        dim3 g(G3/96, BNR/64);
        k_gru_fused<HG, CC><<<g, 256>>>(hA, ldah, p_HS + (size_t)t*CC, TT*CC,
                                        p_Wc0, p_bih0p, p_bhh0p, p_ys0 + (size_t)t*HG);
    }
    // GRU layer 1 (fused x-projection, KX=192 from ys0 rows)
    for (int t = 0; t < TT; t++){
        const float* hA = (t == 0) ? p_zero : (p_ys1 + (size_t)(t-1)*HG);
        int ldah = (t == 0) ? 0 : TT*HG;
        dim3 g(G3/96, BNR/64);
        k_gru_fused<HG, HG><<<g, 256>>>(hA, ldah, p_ys0 + (size_t)t*HG, TT*HG,
                                        p_Wc1, p_bih1p, p_bhh1p, p_ys1 + (size_t)t*HG);
    }

    // pooling + head
    k_pool<<<BNR, 192>>>(p_ys1, att_w, fc1_b, fc2_b, out);
}

// round 16
// speedup vs baseline: 1.4986x; 1.0879x over previous
#include <cuda_runtime.h>
#include <math.h>

#define NNODE 1000
#define TT 12
#define BB 32
#define BT 384
#define CC 96
#define HG 192
#define G3 576
#define BNR 32000
#define DA 32
#define DE 10
#define HOR 12
#define LN_EPS 1e-5f

// ---------------- consolidated big scratch (offsets in floats) ----------------
#define OFF_HS  ((size_t)0)
#define OFF_H   ((size_t)36864000)
#define OFF_Z   ((size_t)73728000)
#define OFF_YS0 ((size_t)110592000)
#define OFF_YS1 ((size_t)184320000)
#define BIG_FLOATS ((size_t)258048000)
__device__ float g_big[BIG_FLOATS];

__device__ float g_Aadp[NNODE*NNODE];
__device__ float g_S[NNODE*NNODE];
__device__ float g_rs[3*NNODE];
__device__ float g_Wt[NNODE*DA];
__device__ float g_P[4*NNODE*DA];
__device__ float g_scpart[3*NNODE];
__device__ float g_cons[8];
__device__ float g_dWc[CC];
__device__ float g_dbc[CC];
__device__ float g_dinv[NNODE];
__device__ float g_Y[BT*NNODE];
__device__ float g_zero[HG];            // never written: GRU h0
__device__ float g_Wc0[G3*(HG+CC)];     // [Whh0p | Wih0p], 576 x 288
__device__ float g_Wc1[G3*(HG+HG)];     // [Whh1p | Wih1p], 576 x 384
__device__ float g_bih0p[G3];
__device__ float g_bhh0p[G3];
__device__ float g_bih1p[G3];
__device__ float g_bhh1p[G3];
__device__ float g_fc1t[HG*HG];
__device__ float g_fc2t[HG*HOR];

__device__ __forceinline__ float sigf(float x){ return 1.0f/(1.0f+expf(-x)); }
__device__ __forceinline__ float gelu_t(float x){
    float x3 = x*x*x;
    return 0.5f*x*(1.0f + tanhf(0.7978845608028654f*(x + 0.044715f*x3)));
}

// ---------------- packed f32x2 helpers (sm_103a FFMA2) ----------------
__device__ __forceinline__ unsigned long long pack2dup(float a){
    unsigned long long r;
    asm("mov.b64 %0, {%1, %1};" : "=l"(r) : "f"(a));
    return r;
}
__device__ __forceinline__ void fma2(unsigned long long& d, unsigned long long a, unsigned long long b){
    asm("fma.rn.f32x2 %0, %1, %2, %0;" : "+l"(d) : "l"(a), "l"(b));
}
__device__ __forceinline__ void unpack2(unsigned long long v, float& lo, float& hi){
    asm("mov.b64 {%0, %1}, %2;" : "=f"(lo), "=f"(hi) : "l"(v));
}

// ---------------- cp.async helpers ----------------
__device__ __forceinline__ void cp4(void* smem, const void* g){
    unsigned sa = (unsigned)__cvta_generic_to_shared(smem);
    asm volatile("cp.async.ca.shared.global [%0], [%1], 4;" :: "r"(sa), "l"(g));
}
__device__ __forceinline__ void cp_commit(){ asm volatile("cp.async.commit_group;"); }
template<int N>
__device__ __forceinline__ void cp_wait(){ asm volatile("cp.async.wait_group %0;" :: "n"(N)); }

// ---------------- prep ----------------
__global__ void k_transp(const float* __restrict__ src, float* __restrict__ dst, int R, int C){
    int i = blockIdx.x*256 + threadIdx.x;
    if (i < R*C){ int r = i / C, c = i % C; dst[c*R + r] = src[i]; }
}

__global__ void k_rowsums(const float* __restrict__ A, const float* __restrict__ F, const float* __restrict__ D){
    __shared__ float red[256];
    int n = blockIdx.x, tid = threadIdx.x;
    float s[3] = {0.f,0.f,0.f};
    for (int m = tid; m < NNODE; m += 256){
        s[0] += A[n*NNODE+m]; s[1] += F[n*NNODE+m]; s[2] += D[n*NNODE+m];
    }
    for (int k = 0; k < 3; k++){
        red[tid] = s[k]; __syncthreads();
        for (int st = 128; st > 0; st >>= 1){ if (tid < st) red[tid] += red[tid+st]; __syncthreads(); }
        if (tid == 0) g_rs[k*NNODE+n] = red[0];
        __syncthreads();
    }
}

__global__ void k_adapt(const float* __restrict__ E1, const float* __restrict__ E2){
    __shared__ float e[NNODE];
    __shared__ float red[256];
    int n = blockIdx.x, tid = threadIdx.x;
    float e1[DE];
#pragma unroll
    for (int d = 0; d < DE; d++) e1[d] = E1[n*DE + d];
    float lmax = -1e30f;
    for (int m = tid; m < NNODE; m += 256){
        float dot = 0.f;
#pragma unroll
        for (int d = 0; d < DE; d++) dot += e1[d]*E2[m*DE + d];
        dot = fmaxf(dot, 0.f);
        e[m] = dot; lmax = fmaxf(lmax, dot);
    }
    red[tid] = lmax; __syncthreads();
    for (int st = 128; st > 0; st >>= 1){ if (tid < st) red[tid] = fmaxf(red[tid], red[tid+st]); __syncthreads(); }
    float mx = red[0]; __syncthreads();
    float ls = 0.f;
    for (int m = tid; m < NNODE; m += 256){ float ex = expf(e[m]-mx); e[m] = ex; ls += ex; }
    red[tid] = ls; __syncthreads();
    for (int st = 128; st > 0; st >>= 1){ if (tid < st) red[tid] += red[tid+st]; __syncthreads(); }
    float inv = 1.0f/red[0];
    for (int m = tid; m < NNODE; m += 256) g_Aadp[n*NNODE+m] = e[m]*inv;
}

__global__ void k_proj(const float* __restrict__ A, const float* __restrict__ F, const float* __restrict__ D){
    __shared__ float r[4][NNODE];
    int n = blockIdx.x, tid = threadIdx.x;  // 128 threads
    for (int m = tid; m < NNODE; m += 128){
        r[0][m] = A[n*NNODE+m]; r[1][m] = F[n*NNODE+m]; r[2][m] = D[n*NNODE+m]; r[3][m] = g_Aadp[n*NNODE+m];
    }
    __syncthreads();
    int w = tid >> 5, a = tid & 31;
    float acc = 0.f;
    for (int m = 0; m < NNODE; m++) acc += r[w][m]*g_Wt[m*DA + a];
    g_P[w*(NNODE*DA) + n*DA + a] = acc;
}

__global__ void k_scorepart(const float* __restrict__ fus_b, const float* __restrict__ fus_v,
                            const float* __restrict__ beta1, const float* __restrict__ beta2){
    int n = blockIdx.x, a = threadIdx.x; // 32 threads
    float w1 = sigf(beta1[0]), w2 = sigf(beta2[0]);
    float pA = g_P[0*NNODE*DA + n*DA + a];
    float pF = g_P[1*NNODE*DA + n*DA + a];
    float pD = g_P[2*NNODE*DA + n*DA + a];
    float pP = g_P[3*NNODE*DA + n*DA + a];
    float fb = fus_b[a], fv = fus_v[a];
    float t0 = tanhf(0.5f*pA + 0.5f*pP + fb)*fv;
    float t1 = tanhf(w1*pA + (1.f-w1)*pF + fb)*fv;
    float t2 = tanhf(w2*pA + (1.f-w2)*pD + fb)*fv;
#pragma unroll
    for (int s = 16; s > 0; s >>= 1){
        t0 += __shfl_down_sync(0xffffffffu, t0, s);
        t1 += __shfl_down_sync(0xffffffffu, t1, s);
        t2 += __shfl_down_sync(0xffffffffu, t2, s);
    }
    if (a == 0){ g_scpart[0*NNODE+n]=t0; g_scpart[1*NNODE+n]=t1; g_scpart[2*NNODE+n]=t2; }
}

__global__ void k_finalize(const float* __restrict__ beta1, const float* __restrict__ beta2,
                           const float* __restrict__ W1, const float* __restrict__ b1){
    __shared__ float red[1024];
    __shared__ float sc[3];
    __shared__ float st[6];
    int tid = threadIdx.x;
    for (int k = 0; k < 3; k++){
        red[tid] = (tid < NNODE) ? g_scpart[k*NNODE + tid] : 0.f;
        __syncthreads();
        for (int s = 512; s > 0; s >>= 1){ if (tid < s) red[tid] += red[tid+s]; __syncthreads(); }
        if (tid == 0) sc[k] = red[0] / (float)NNODE;
        __syncthreads();
    }
    red[tid] = (tid < CC) ? W1[tid] : 0.f; __syncthreads();
    for (int s = 512; s > 0; s >>= 1){ if (tid < s) red[tid] += red[tid+s]; __syncthreads(); }
    if (tid == 0) st[0] = red[0]/(float)CC;
    __syncthreads();
    red[tid] = (tid < CC) ? b1[tid] : 0.f; __syncthreads();
    for (int s = 512; s > 0; s >>= 1){ if (tid < s) red[tid] += red[tid+s]; __syncthreads(); }
    if (tid == 0) st[1] = red[0]/(float)CC;
    __syncthreads();
    float dw = 0.f, db = 0.f;
    if (tid < CC){
        dw = W1[tid] - st[0]; db = b1[tid] - st[1];
        g_dWc[tid] = dw; g_dbc[tid] = db;
    }
    red[tid] = dw*dw; __syncthreads();
    for (int s = 512; s > 0; s >>= 1){ if (tid < s) red[tid] += red[tid+s]; __syncthreads(); }
    if (tid == 0) st[2] = red[0]/(float)CC;
    __syncthreads();
    red[tid] = dw*db; __syncthreads();
    for (int s = 512; s > 0; s >>= 1){ if (tid < s) red[tid] += red[tid+s]; __syncthreads(); }
    if (tid == 0) st[3] = red[0]/(float)CC;
    __syncthreads();
    red[tid] = db*db; __syncthreads();
    for (int s = 512; s > 0; s >>= 1){ if (tid < s) red[tid] += red[tid+s]; __syncthreads(); }
    if (tid == 0) st[4] = red[0]/(float)CC;
    __syncthreads();
    if (tid == 0){
        float w1 = sigf(beta1[0]), w2 = sigf(beta2[0]);
        float m = fmaxf(sc[0], fmaxf(sc[1], sc[2]));
        float e0 = expf(sc[0]-m), e1 = expf(sc[1]-m), e2 = expf(sc[2]-m);
        float is = 1.f/(e0+e1+e2);
        float a0 = e0*is, a1 = e1*is, a2 = e2*is;
        g_cons[0] = 0.5f*a0 + w1*a1 + w2*a2;
        g_cons[1] = a1*(1.f-w1);
        g_cons[2] = a2*(1.f-w2);
        g_cons[3] = 0.5f*a0;
        g_cons[4] = st[2];
        g_cons[5] = st[3];
        g_cons[6] = st[4];
    }
    __syncthreads();
    if (tid < NNODE){
        float d = g_cons[0]*g_rs[tid] + g_cons[1]*g_rs[NNODE+tid] + g_cons[2]*g_rs[2*NNODE+tid] + g_cons[3] + 1.0f;
        g_dinv[tid] = rsqrtf(fmaxf(d, 1e-12f));
    }
}

__global__ void k_shat(const float* __restrict__ A, const float* __restrict__ F, const float* __restrict__ D){
    int idx = blockIdx.x*256 + threadIdx.x;
    if (idx >= NNODE*NNODE) return;
    int n = idx / NNODE, m = idx - n*NNODE;
    float v = g_cons[0]*A[idx] + g_cons[1]*F[idx] + g_cons[2]*D[idx] + g_cons[3]*g_Aadp[idx];
    if (n == m) v += 1.0f;
    g_S[idx] = v * g_dinv[n]*g_dinv[m];
}

// permute GRU weight rows (g*HG+c -> 3c+g) into combined matrix at column offset
__global__ void k_permW2(const float* __restrict__ W, float* __restrict__ Wp,
                         int K, int dstStride, int colOff){
    int idx = blockIdx.x*256 + threadIdx.x;
    if (idx < G3*K){
        int row = idx / K, k = idx - row*K;
        int g = row / HG, c = row - g*HG;
        Wp[(size_t)(3*c+g)*dstStride + colOff + k] = W[idx];
    }
}

__global__ void k_permB(const float* __restrict__ b0, const float* __restrict__ b1,
                        const float* __restrict__ b2, const float* __restrict__ b3,
                        float* __restrict__ p0, float* __restrict__ p1,
                        float* __restrict__ p2, float* __restrict__ p3){
    int idx = blockIdx.x*256 + threadIdx.x;
    if (idx < G3){
        int g = idx / HG, c = idx - g*HG;
        int d = 3*c+g;
        p0[d] = b0[idx]; p1[d] = b1[idx]; p2[d] = b2[idx]; p3[d] = b3[idx];
    }
}

// GCN layer1 elementwise (LN-of-affine-in-scalar trick)
__global__ void k_gcn1(const float* __restrict__ g1, const float* __restrict__ bln1,
                       float* __restrict__ H){
    int idx = blockIdx.x*256 + threadIdx.x;
    if (idx >= BT*NNODE*CC) return;
    int row = idx / CC, c = idx - row*CC;
    float y = __ldg(&g_Y[row]);
    float diff = y*g_dWc[c] + g_dbc[c];
    float var = y*y*g_cons[4] + 2.f*y*g_cons[5] + g_cons[6];
    float h = diff*rsqrtf(var + LN_EPS)*g1[c] + bln1[c];
    H[idx] = fmaxf(h, 0.f);
}

// ---------------- GEMMs: 64x96 tile, BK=32, 256 threads, 4x6 per thread, FFMA2 core ----------------
template<bool GUARD>
__global__ __launch_bounds__(256) void k_gemm_nt(const float* __restrict__ A, int lda,
                          const float* __restrict__ B, int ldb,
                          float* __restrict__ C, int ldc,
                          int M, int N, int K, const float* __restrict__ bias){
    __shared__ __align__(16) float As[64][33];
    __shared__ __align__(16) float Bs[32][98];
    int tid = threadIdx.x;
    int tx = tid & 15, ty = tid >> 4;
    int m0 = blockIdx.y*64, n0 = blockIdx.x*96;
    unsigned long long acc[4][3];
#pragma unroll
    for (int i = 0; i < 4; i++)
#pragma unroll
        for (int p = 0; p < 3; p++) acc[i][p] = 0ULL;
    for (int k0 = 0; k0 < K; k0 += 32){
#pragma unroll
        for (int e = tid; e < 2048; e += 256){
            int r = e >> 5, c = e & 31;
            float v;
            if (GUARD) v = (m0+r < M && k0+c < K) ? A[(size_t)(m0+r)*lda + k0+c] : 0.f;
            else       v = A[(size_t)(m0+r)*lda + k0+c];
            As[r][c] = v;
        }
#pragma unroll
        for (int e = tid; e < 3072; e += 256){
            int j = e >> 5, c = e & 31;
            float v;
            if (GUARD) v = (n0+j < N && k0+c < K) ? B[(size_t)(n0+j)*ldb + k0+c] : 0.f;
            else       v = B[(size_t)(n0+j)*ldb + k0+c];
            Bs[c][j] = v;
        }
        __syncthreads();
#pragma unroll
        for (int kk = 0; kk < 32; kk++){
            unsigned long long a2[4], b2[3];
            const unsigned long long* brow = reinterpret_cast<const unsigned long long*>(&Bs[kk][0]);
#pragma unroll
            for (int i = 0; i < 4; i++) a2[i] = pack2dup(As[ty*4+i][kk]);
#pragma unroll
            for (int p = 0; p < 3; p++) b2[p] = brow[tx*3+p];
#pragma unroll
            for (int i = 0; i < 4; i++)
#pragma unroll
                for (int p = 0; p < 3; p++) fma2(acc[i][p], a2[i], b2[p]);
        }
        __syncthreads();
    }
#pragma unroll
    for (int i = 0; i < 4; i++){
        int gr = m0 + ty*4 + i;
        if (GUARD && gr >= M) continue;
        float v[6];
#pragma unroll
        for (int p = 0; p < 3; p++) unpack2(acc[i][p], v[2*p], v[2*p+1]);
#pragma unroll
        for (int j = 0; j < 6; j++){
            int gc = n0 + tx*6 + j;
            if (GUARD && gc >= N) continue;
            float w = v[j];
            if (bias) w += bias[gc];
            C[(size_t)gr*ldc + gc] = w;
        }
    }
}

template<bool GUARD>
__global__ __launch_bounds__(256) void k_gemm_nn(const float* __restrict__ A, int lda,
                          const float* __restrict__ Bbase, int ldb, int bstride,
                          float* __restrict__ Cbase, int ldc, int cstride,
                          int M, int N, int K){
    const float* B = Bbase + (size_t)blockIdx.z*bstride;
    float* C = Cbase + (size_t)blockIdx.z*cstride;
    __shared__ __align__(16) float As[64][33];
    __shared__ __align__(16) float Bs[32][98];
    int tid = threadIdx.x;
    int tx = tid & 15, ty = tid >> 4;
    int m0 = blockIdx.y*64, n0 = blockIdx.x*96;
    unsigned long long acc[4][3];
#pragma unroll
    for (int i = 0; i < 4; i++)
#pragma unroll
        for (int p = 0; p < 3; p++) acc[i][p] = 0ULL;
    for (int k0 = 0; k0 < K; k0 += 32){
#pragma unroll
        for (int e = tid; e < 2048; e += 256){
            int r = e >> 5, c = e & 31;
            float v;
            if (GUARD) v = (m0+r < M && k0+c < K) ? A[(size_t)(m0+r)*lda + k0+c] : 0.f;
            else       v = A[(size_t)(m0+r)*lda + k0+c];
            As[r][c] = v;
        }
#pragma unroll
        for (int e = tid; e < 3072; e += 256){
            int kk = e / 96, j = e - kk*96;
            float v;
            if (GUARD) v = (k0+kk < K && n0+j < N) ? B[(size_t)(k0+kk)*ldb + n0+j] : 0.f;
            else       v = B[(size_t)(k0+kk)*ldb + n0+j];
            Bs[kk][j] = v;
        }
        __syncthreads();
#pragma unroll
        for (int kk = 0; kk < 32; kk++){
            unsigned long long a2[4], b2[3];
            const unsigned long long* brow = reinterpret_cast<const unsigned long long*>(&Bs[kk][0]);
#pragma unroll
            for (int i = 0; i < 4; i++) a2[i] = pack2dup(As[ty*4+i][kk]);
#pragma unroll
            for (int p = 0; p < 3; p++) b2[p] = brow[tx*3+p];
#pragma unroll
            for (int i = 0; i < 4; i++)
#pragma unroll
                for (int p = 0; p < 3; p++) fma2(acc[i][p], a2[i], b2[p]);
        }
        __syncthreads();
    }
#pragma unroll
    for (int i = 0; i < 4; i++){
        int gr = m0 + ty*4 + i;
        if (GUARD && gr >= M) continue;
        float v[6];
#pragma unroll
        for (int p = 0; p < 3; p++) unpack2(acc[i][p], v[2*p], v[2*p+1]);
#pragma unroll
        for (int j = 0; j < 6; j++){
            int gc = n0 + tx*6 + j;
            if (GUARD && gc >= N) continue;
            C[(size_t)gr*ldc + gc] = v[j];
        }
    }
}

// Z @ W2 + b2 -> LN(ln2) -> write in natural (b,t,n,c) order (raw-view reshape semantics)
__global__ __launch_bounds__(256) void k_gemm_nn_ln(const float* __restrict__ A,   // Z, lda=96
                             const float* __restrict__ W2,  // 96x96
                             const float* __restrict__ b2,
                             const float* __restrict__ g2,
                             const float* __restrict__ bln2,
                             float* __restrict__ HS){
    __shared__ __align__(16) float As[64][33];
    __shared__ __align__(16) float Bs[32][98];
    __shared__ float red[64][17];
    int tid = threadIdx.x;
    int tx = tid & 15, ty = tid >> 4;
    int m0 = blockIdx.y*64;
    unsigned long long acc[4][3];
#pragma unroll
    for (int i = 0; i < 4; i++)
#pragma unroll
        for (int p = 0; p < 3; p++) acc[i][p] = 0ULL;
    for (int k0 = 0; k0 < 96; k0 += 32){
#pragma unroll
        for (int e = tid; e < 2048; e += 256){
            int r = e >> 5, c = e & 31;
            As[r][c] = A[(size_t)(m0+r)*96 + k0+c];
        }
#pragma unroll
        for (int e = tid; e < 3072; e += 256){
            int kk = e / 96, j = e - kk*96;
            Bs[kk][j] = W2[(k0+kk)*96 + j];
        }
        __syncthreads();
#pragma unroll
        for (int kk = 0; kk < 32; kk++){
            unsigned long long a2[4], b2[3];
            const unsigned long long* brow = reinterpret_cast<const unsigned long long*>(&Bs[kk][0]);
#pragma unroll
            for (int i = 0; i < 4; i++) a2[i] = pack2dup(As[ty*4+i][kk]);
#pragma unroll
            for (int p = 0; p < 3; p++) b2[p] = brow[tx*3+p];
#pragma unroll
            for (int i = 0; i < 4; i++)
#pragma unroll
                for (int p = 0; p < 3; p++) fma2(acc[i][p], a2[i], b2[p]);
        }
        __syncthreads();
    }
    float v[4][6];
#pragma unroll
    for (int i = 0; i < 4; i++){
#pragma unroll
        for (int p = 0; p < 3; p++) unpack2(acc[i][p], v[i][2*p], v[i][2*p+1]);
#pragma unroll
        for (int j = 0; j < 6; j++) v[i][j] += b2[tx*6+j];
    }
#pragma unroll
    for (int i = 0; i < 4; i++){
        float p = 0.f;
#pragma unroll
        for (int j = 0; j < 6; j++) p += v[i][j];
        red[ty*4+i][tx] = p;
    }
    __syncthreads();
    float mean[4];
#pragma unroll
    for (int i = 0; i < 4; i++){
        float s = 0.f;
#pragma unroll
        for (int q = 0; q < 16; q++) s += red[ty*4+i][q];
        mean[i] = s * (1.0f/96.0f);
    }
    __syncthreads();
#pragma unroll
    for (int i = 0; i < 4; i++){
        float p = 0.f;
#pragma unroll
        for (int j = 0; j < 6; j++){ float d = v[i][j]-mean[i]; p += d*d; }
        red[ty*4+i][tx] = p;
    }
    __syncthreads();
#pragma unroll
    for (int i = 0; i < 4; i++){
        float s = 0.f;
#pragma unroll
        for (int q = 0; q < 16; q++) s += red[ty*4+i][q];
        float rstd = rsqrtf(s*(1.0f/96.0f) + LN_EPS);
        int R = m0 + ty*4 + i;
        size_t base = (size_t)R*96;         // RAW VIEW: identity layout
#pragma unroll
        for (int j = 0; j < 6; j++){
            int col = tx*6 + j;
            HS[base + col] = (v[i][j]-mean[i])*rstd*g2[col] + bln2[col];
        }
    }
}

// Fused GRU step with cp.async double-buffered pipeline.
// acc_h = h_prev @ Whhp^T (chunks [0, KH/32)), acc_x = x_t @ Wihp^T (chunks [KH/32, NCH)).
template<int KH, int KX>
__global__ __launch_bounds__(256) void k_gru_fused(
    const float* __restrict__ Ah, int ldah,      // h_prev rows (lda=0 -> zero buffer)
    const float* __restrict__ Ax, int ldax,      // x_t rows (pre-offset to slice)
    const float* __restrict__ B,                 // combined 576 x (KH+KX)
    const float* __restrict__ bih, const float* __restrict__ bhh,  // permuted
    float* __restrict__ ys){                     // + t*192, row stride 2304
    constexpr int KT = KH + KX;
    constexpr int NCH = KT / 32;
    constexpr int CH_H = KH / 32;
    __shared__ __align__(16) float As[2][64][33];
    __shared__ __align__(16) float Bs[2][32][98];
    int tid = threadIdx.x;
    int tx = tid & 15, ty = tid >> 4;
    int m0 = blockIdx.y*64, n0 = blockIdx.x*96;
    unsigned long long ah[4][3], ax[4][3];
#pragma unroll
    for (int i = 0; i < 4; i++)
#pragma unroll
        for (int p = 0; p < 3; p++){ ah[i][p] = 0ULL; ax[i][p] = 0ULL; }

    auto load_chunk = [&](int q, int s){
        const float* Asrc; int ldA; int kof;
        if (q < CH_H){ Asrc = Ah; ldA = ldah; kof = q*32; }
        else         { Asrc = Ax; ldA = ldax; kof = (q-CH_H)*32; }
#pragma unroll
        for (int e = tid; e < 2048; e += 256){
            int r = e >> 5, c = e & 31;
            cp4(&As[s][r][c], Asrc + (size_t)(m0+r)*ldA + kof + c);
        }
        int bk = q*32;
#pragma unroll
        for (int e = tid; e < 3072; e += 256){
            int j = e >> 5, c = e & 31;
            cp4(&Bs[s][c][j], B + (size_t)(n0+j)*KT + bk + c);
        }
        cp_commit();
    };

    load_chunk(0, 0);
#pragma unroll
    for (int q = 0; q < NCH; q++){
        if (q+1 < NCH) load_chunk(q+1, (q+1)&1);
        if (q+1 < NCH) cp_wait<1>(); else cp_wait<0>();
        __syncthreads();
        int s = q & 1;
        if (q < CH_H){
#pragma unroll
            for (int kk = 0; kk < 32; kk++){
                unsigned long long a2[4], b2[3];
                const unsigned long long* brow = reinterpret_cast<const unsigned long long*>(&Bs[s][kk][0]);
#pragma unroll
                for (int i = 0; i < 4; i++) a2[i] = pack2dup(As[s][ty*4+i][kk]);
#pragma unroll
                for (int p = 0; p < 3; p++) b2[p] = brow[tx*3+p];
#pragma unroll
                for (int i = 0; i < 4; i++)
#pragma unroll
                    for (int p = 0; p < 3; p++) fma2(ah[i][p], a2[i], b2[p]);
            }
        } else {
#pragma unroll
            for (int kk = 0; kk < 32; kk++){
                unsigned long long a2[4], b2[3];
                const unsigned long long* brow = reinterpret_cast<const unsigned long long*>(&Bs[s][kk][0]);
#pragma unroll
                for (int i = 0; i < 4; i++) a2[i] = pack2dup(As[s][ty*4+i][kk]);
#pragma unroll
                for (int p = 0; p < 3; p++) b2[p] = brow[tx*3+p];
#pragma unroll
                for (int i = 0; i < 4; i++)
#pragma unroll
                    for (int p = 0; p < 3; p++) fma2(ax[i][p], a2[i], b2[p]);
            }
        }
        __syncthreads();
    }

    int j0 = n0 + tx*6;
    int c0 = j0 / 3;
#pragma unroll
    for (int i = 0; i < 4; i++){
        int row = m0 + ty*4 + i;
        float vh[6], vx[6];
#pragma unroll
        for (int p = 0; p < 3; p++){ unpack2(ah[i][p], vh[2*p], vh[2*p+1]); unpack2(ax[i][p], vx[2*p], vx[2*p+1]); }
#pragma unroll
        for (int p = 0; p < 2; p++){
            int j = j0 + p*3;
            int c = c0 + p;
            float hprev = Ah[(size_t)row*ldah + c];   // lda=0 -> g_zero[c]=0 at t=0
            float r = sigf(vx[p*3]   + bih[j]   + vh[p*3]   + bhh[j]);
            float z = sigf(vx[p*3+1] + bih[j+1] + vh[p*3+1] + bhh[j+1]);
            float nn = tanhf(vx[p*3+2] + bih[j+2] + r*(vh[p*3+2] + bhh[j+2]));
            ys[(size_t)row*2304 + c] = (1.f-z)*nn + z*hprev;
        }
    }
}

// Attention pooling + FC head
__global__ void k_pool(const float* __restrict__ ys, const float* __restrict__ attw,
                       const float* __restrict__ fc1b, const float* __restrict__ fc2b,
                       float* __restrict__ out){
    __shared__ float sOut[12][193];
    __shared__ float sAtt[12];
    __shared__ float sCtx[192];
    __shared__ float sHfc[192];
    __shared__ float red2[16][12];
    int bn = blockIdx.x, tid = threadIdx.x;  // 192 threads
#pragma unroll
    for (int t = 0; t < 12; t++) sOut[t][tid] = ys[(size_t)bn*2304 + t*192 + tid];
    __syncthreads();
    int w = tid >> 5, l = tid & 31;
#pragma unroll
    for (int q = 0; q < 2; q++){
        int t = 2*w + q;
        float p = 0.f;
#pragma unroll
        for (int s = 0; s < 6; s++) p += sOut[t][l + 32*s]*attw[l + 32*s];
#pragma unroll
        for (int s = 16; s > 0; s >>= 1) p += __shfl_down_sync(0xffffffffu, p, s);
        if (l == 0) sAtt[t] = p;
    }
    __syncthreads();
    if (tid == 0){
        float mx = -1e30f;
        for (int t = 0; t < 12; t++) mx = fmaxf(mx, sAtt[t]);
        float s = 0.f;
        for (int t = 0; t < 12; t++){ sAtt[t] = expf(sAtt[t]-mx); s += sAtt[t]; }
        float inv = 1.f/s;
        for (int t = 0; t < 12; t++) sAtt[t] *= inv;
    }
    __syncthreads();
    float c = 0.f;
#pragma unroll
    for (int t = 0; t < 12; t++) c += sAtt[t]*sOut[t][tid];
    sCtx[tid] = c;
    __syncthreads();
    float a0 = 0.f, a1 = 0.f, a2 = 0.f, a3 = 0.f;
#pragma unroll 4
    for (int k = 0; k < 192; k += 4){
        a0 += sCtx[k]  *g_fc1t[(k)*192 + tid];
        a1 += sCtx[k+1]*g_fc1t[(k+1)*192 + tid];
        a2 += sCtx[k+2]*g_fc1t[(k+2)*192 + tid];
        a3 += sCtx[k+3]*g_fc1t[(k+3)*192 + tid];
    }
    sHfc[tid] = gelu_t(fc1b[tid] + ((a0+a1)+(a2+a3)));
    __syncthreads();
    int o = tid % 12, grp = tid / 12;
    float p2 = 0.f;
    for (int j = grp; j < 192; j += 16) p2 += sHfc[j]*g_fc2t[j*12 + o];
    red2[grp][o] = p2;
    __syncthreads();
    if (tid < 12){
        float s = fc2b[tid];
#pragma unroll
        for (int q = 0; q < 16; q++) s += red2[q][tid];
        int b = bn / 1000, n = bn - b*1000;
        out[(size_t)(b*12 + tid)*1000 + n] = s;
    }
}

// ---------------- host launcher ----------------
extern "C" void kernel_launch(void* const* d_in, const int* in_sizes, int n_in,
                              void* d_out, int out_size){
    const float* x      = (const float*)d_in[0];
    const float* A      = (const float*)d_in[1];
    const float* FSP    = (const float*)d_in[2];
    const float* DSP    = (const float*)d_in[3];
    const float* E1     = (const float*)d_in[4];
    const float* E2     = (const float*)d_in[5];
    const float* fus_W  = (const float*)d_in[6];
    const float* fus_b  = (const float*)d_in[7];
    const float* fus_v  = (const float*)d_in[8];
    const float* beta1  = (const float*)d_in[9];
    const float* beta2  = (const float*)d_in[10];
    const float* gcn_W1 = (const float*)d_in[11];
    const float* gcn_b1 = (const float*)d_in[12];
    const float* ln1_g  = (const float*)d_in[13];
    const float* ln1_b  = (const float*)d_in[14];
    const float* gcn_W2 = (const float*)d_in[15];
    const float* gcn_b2 = (const float*)d_in[16];
    const float* ln2_g  = (const float*)d_in[17];
    const float* ln2_b  = (const float*)d_in[18];
    const float* Wih0   = (const float*)d_in[19];
    const float* Whh0   = (const float*)d_in[20];
    const float* bih0   = (const float*)d_in[21];
    const float* bhh0   = (const float*)d_in[22];
    const float* Wih1   = (const float*)d_in[23];
    const float* Whh1   = (const float*)d_in[24];
    const float* bih1   = (const float*)d_in[25];
    const float* bhh1   = (const float*)d_in[26];
    const float* att_w  = (const float*)d_in[27];
    const float* fc1_W  = (const float*)d_in[28];
    const float* fc1_b  = (const float*)d_in[29];
    const float* fc2_W  = (const float*)d_in[30];
    const float* fc2_b  = (const float*)d_in[31];
    float* out = (float*)d_out;

    float *p_big, *p_Wt, *p_S, *p_Y, *p_zero, *p_Wc0, *p_Wc1;
    float *p_bih0p, *p_bhh0p, *p_bih1p, *p_bhh1p;
    float *p_fc1t, *p_fc2t;
    cudaGetSymbolAddress((void**)&p_big, g_big);
    cudaGetSymbolAddress((void**)&p_Wt, g_Wt);
    cudaGetSymbolAddress((void**)&p_S, g_S);
    cudaGetSymbolAddress((void**)&p_Y, g_Y);
    cudaGetSymbolAddress((void**)&p_zero, g_zero);
    cudaGetSymbolAddress((void**)&p_Wc0, g_Wc0);
    cudaGetSymbolAddress((void**)&p_Wc1, g_Wc1);
    cudaGetSymbolAddress((void**)&p_bih0p, g_bih0p);
    cudaGetSymbolAddress((void**)&p_bhh0p, g_bhh0p);
    cudaGetSymbolAddress((void**)&p_bih1p, g_bih1p);
    cudaGetSymbolAddress((void**)&p_bhh1p, g_bhh1p);
    cudaGetSymbolAddress((void**)&p_fc1t, g_fc1t);
    cudaGetSymbolAddress((void**)&p_fc2t, g_fc2t);

    float* p_HS  = p_big + OFF_HS;
    float* p_H   = p_big + OFF_H;
    float* p_Z   = p_big + OFF_Z;
    float* p_ys0 = p_big + OFF_YS0;
    float* p_ys1 = p_big + OFF_YS1;

    // graph construction
    k_transp<<<(DA*NNODE+255)/256, 256>>>(fus_W, p_Wt, DA, NNODE);
    k_rowsums<<<NNODE, 256>>>(A, FSP, DSP);
    k_adapt<<<NNODE, 256>>>(E1, E2);
    k_proj<<<NNODE, 128>>>(A, FSP, DSP);
    k_scorepart<<<NNODE, 32>>>(fus_b, fus_v, beta1, beta2);
    k_finalize<<<1, 1024>>>(beta1, beta2, gcn_W1, gcn_b1);
    k_shat<<<(NNODE*NNODE+255)/256, 256>>>(A, FSP, DSP);

    // weight prep: combined permuted GRU weights + permuted biases
    k_permW2<<<(G3*HG+255)/256, 256>>>(Whh0, p_Wc0, HG, HG+CC, 0);
    k_permW2<<<(G3*CC+255)/256, 256>>>(Wih0, p_Wc0, CC, HG+CC, HG);
    k_permW2<<<(G3*HG+255)/256, 256>>>(Whh1, p_Wc1, HG, HG+HG, 0);
    k_permW2<<<(G3*HG+255)/256, 256>>>(Wih1, p_Wc1, HG, HG+HG, HG);
    k_permB<<<(G3+255)/256, 256>>>(bih0, bhh0, bih1, bhh1, p_bih0p, p_bhh0p, p_bih1p, p_bhh1p);
    k_transp<<<(HG*HG+255)/256, 256>>>(fc1_W, p_fc1t, HG, HG);
    k_transp<<<(HOR*HG+255)/256, 256>>>(fc2_W, p_fc2t, HOR, HG);

    // GCN
    {   dim3 g((NNODE+95)/96, (BT+63)/64);
        k_gemm_nt<true><<<g, 256>>>(x, NNODE, p_S, NNODE, p_Y, NNODE, BT, NNODE, NNODE, nullptr);
    }
    k_gcn1<<<(BT*NNODE*CC+255)/256, 256>>>(ln1_g, ln1_b, p_H);
    {   dim3 g(1, (NNODE+63)/64, BT);
        k_gemm_nn<true><<<g, 256>>>(p_S, NNODE, p_H, CC, NNODE*CC, p_Z, CC, NNODE*CC, NNODE, CC, NNODE);
    }
    {   dim3 g(1, (BT*NNODE)/64);
        k_gemm_nn_ln<<<g, 256>>>(p_Z, gcn_W2, gcn_b2, ln2_g, ln2_b, p_HS);
    }

    // GRU layer 0 (fused x-projection, KX=96 from HS raw-view rows)
    for (int t = 0; t < TT; t++){
        const float* hA = (t == 0) ? p_zero : (p_ys0 + (size_t)(t-1)*HG);
        int ldah = (t == 0) ? 0 : TT*HG;
        dim3 g(G3/96, BNR/64);
        k_gru_fused<HG, CC><<<g, 256>>>(hA, ldah, p_HS + (size_t)t*CC, TT*CC,
                                        p_Wc0, p_bih0p, p_bhh0p, p_ys0 + (size_t)t*HG);
    }
    // GRU layer 1 (fused x-projection, KX=192 from ys0 rows)
    for (int t = 0; t < TT; t++){
        const float* hA = (t == 0) ? p_zero : (p_ys1 + (size_t)(t-1)*HG);
        int ldah = (t == 0) ? 0 : TT*HG;
        dim3 g(G3/96, BNR/64);
        k_gru_fused<HG, HG><<<g, 256>>>(hA, ldah, p_ys0 + (size_t)t*HG, TT*HG,
                                        p_Wc1, p_bih1p, p_bhh1p, p_ys1 + (size_t)t*HG);
    }

    // pooling + head
    k_pool<<<BNR, 192>>>(p_ys1, att_w, fc1_b, fc2_b, out);
}

// round 17
// speedup vs baseline: 1.5806x; 1.0547x over previous
#include <cuda_runtime.h>
#include <math.h>

#define NNODE 1000
#define NPAD 1024
#define TT 12
#define BB 32
#define BT 384
#define CC 96
#define HG 192
#define G3 576
#define BNR 32000
#define DA 32
#define DE 10
#define HOR 12
#define LN_EPS 1e-5f

// ---------------- consolidated big scratch (offsets in floats) ----------------
#define OFF_HS  ((size_t)0)
#define OFF_H   ((size_t)36864000)                    // padded H: 384*1024*96
#define OFF_Z   ((size_t)(36864000+37748736))         // 74,612,736
#define OFF_YS0 ((size_t)(74612736+36864000))         // 111,476,736
#define OFF_YS1 ((size_t)(111476736+73728000))        // 185,204,736
#define BIG_FLOATS ((size_t)(185204736+73728000))     // 258,932,736
__device__ float g_big[BIG_FLOATS];

__device__ float g_Aadp[NNODE*NNODE];
__device__ float g_S[NNODE*NPAD];       // padded: cols 1000..1023 zero
__device__ float g_rs[3*NNODE];
__device__ float g_Wt[NNODE*DA];
__device__ float g_P[4*NNODE*DA];
__device__ float g_scpart[3*NNODE];
__device__ float g_cons[8];
__device__ float g_dWc[CC];
__device__ float g_dbc[CC];
__device__ float g_dinv[NNODE];
__device__ float g_Y[BT*NNODE];
__device__ float g_zero[HG];            // never written: GRU h0
__device__ float g_Wc0[G3*(HG+CC)];     // [Whh0p | Wih0p], 576 x 288
__device__ float g_Wc1[G3*(HG+HG)];     // [Whh1p | Wih1p], 576 x 384
__device__ float g_bih0p[G3];
__device__ float g_bhh0p[G3];
__device__ float g_bih1p[G3];
__device__ float g_bhh1p[G3];
__device__ float g_fc1t[HG*HG];
__device__ float g_fc2t[HG*HOR];

__device__ __forceinline__ float sigf(float x){ return 1.0f/(1.0f+expf(-x)); }
__device__ __forceinline__ float gelu_t(float x){
    float x3 = x*x*x;
    return 0.5f*x*(1.0f + tanhf(0.7978845608028654f*(x + 0.044715f*x3)));
}

// ---------------- packed f32x2 helpers (sm_103a FFMA2) ----------------
__device__ __forceinline__ unsigned long long pack2dup(float a){
    unsigned long long r;
    asm("mov.b64 %0, {%1, %1};" : "=l"(r) : "f"(a));
    return r;
}
__device__ __forceinline__ void fma2(unsigned long long& d, unsigned long long a, unsigned long long b){
    asm("fma.rn.f32x2 %0, %1, %2, %0;" : "+l"(d) : "l"(a), "l"(b));
}
__device__ __forceinline__ void unpack2(unsigned long long v, float& lo, float& hi){
    asm("mov.b64 {%0, %1}, %2;" : "=f"(lo), "=f"(hi) : "l"(v));
}

// ---------------- cp.async helpers ----------------
__device__ __forceinline__ void cp4(void* smem, const void* g){
    unsigned sa = (unsigned)__cvta_generic_to_shared(smem);
    asm volatile("cp.async.ca.shared.global [%0], [%1], 4;" :: "r"(sa), "l"(g));
}
__device__ __forceinline__ void cp4z(void* smem, const void* g, bool pred){
    unsigned sa = (unsigned)__cvta_generic_to_shared(smem);
    int sz = pred ? 4 : 0;
    asm volatile("cp.async.ca.shared.global [%0], [%1], 4, %2;" :: "r"(sa), "l"(g), "r"(sz));
}
__device__ __forceinline__ void cp_commit(){ asm volatile("cp.async.commit_group;"); }
template<int N>
__device__ __forceinline__ void cp_wait(){ asm volatile("cp.async.wait_group %0;" :: "n"(N)); }

// ---------------- prep ----------------
__global__ void k_transp(const float* __restrict__ src, float* __restrict__ dst, int R, int C){
    int i = blockIdx.x*256 + threadIdx.x;
    if (i < R*C){ int r = i / C, c = i % C; dst[c*R + r] = src[i]; }
}

__global__ void k_rowsums(const float* __restrict__ A, const float* __restrict__ F, const float* __restrict__ D){
    __shared__ float red[256];
    int n = blockIdx.x, tid = threadIdx.x;
    float s[3] = {0.f,0.f,0.f};
    for (int m = tid; m < NNODE; m += 256){
        s[0] += A[n*NNODE+m]; s[1] += F[n*NNODE+m]; s[2] += D[n*NNODE+m];
    }
    for (int k = 0; k < 3; k++){
        red[tid] = s[k]; __syncthreads();
        for (int st = 128; st > 0; st >>= 1){ if (tid < st) red[tid] += red[tid+st]; __syncthreads(); }
        if (tid == 0) g_rs[k*NNODE+n] = red[0];
        __syncthreads();
    }
}

__global__ void k_adapt(const float* __restrict__ E1, const float* __restrict__ E2){
    __shared__ float e[NNODE];
    __shared__ float red[256];
    int n = blockIdx.x, tid = threadIdx.x;
    float e1[DE];
#pragma unroll
    for (int d = 0; d < DE; d++) e1[d] = E1[n*DE + d];
    float lmax = -1e30f;
    for (int m = tid; m < NNODE; m += 256){
        float dot = 0.f;
#pragma unroll
        for (int d = 0; d < DE; d++) dot += e1[d]*E2[m*DE + d];
        dot = fmaxf(dot, 0.f);
        e[m] = dot; lmax = fmaxf(lmax, dot);
    }
    red[tid] = lmax; __syncthreads();
    for (int st = 128; st > 0; st >>= 1){ if (tid < st) red[tid] = fmaxf(red[tid], red[tid+st]); __syncthreads(); }
    float mx = red[0]; __syncthreads();
    float ls = 0.f;
    for (int m = tid; m < NNODE; m += 256){ float ex = expf(e[m]-mx); e[m] = ex; ls += ex; }
    red[tid] = ls; __syncthreads();
    for (int st = 128; st > 0; st >>= 1){ if (tid < st) red[tid] += red[tid+st]; __syncthreads(); }
    float inv = 1.0f/red[0];
    for (int m = tid; m < NNODE; m += 256) g_Aadp[n*NNODE+m] = e[m]*inv;
}

__global__ void k_proj(const float* __restrict__ A, const float* __restrict__ F, const float* __restrict__ D){
    __shared__ float r[4][NNODE];
    int n = blockIdx.x, tid = threadIdx.x;  // 128 threads
    for (int m = tid; m < NNODE; m += 128){
        r[0][m] = A[n*NNODE+m]; r[1][m] = F[n*NNODE+m]; r[2][m] = D[n*NNODE+m]; r[3][m] = g_Aadp[n*NNODE+m];
    }
    __syncthreads();
    int w = tid >> 5, a = tid & 31;
    float acc = 0.f;
    for (int m = 0; m < NNODE; m++) acc += r[w][m]*g_Wt[m*DA + a];
    g_P[w*(NNODE*DA) + n*DA + a] = acc;
}

__global__ void k_scorepart(const float* __restrict__ fus_b, const float* __restrict__ fus_v,
                            const float* __restrict__ beta1, const float* __restrict__ beta2){
    int n = blockIdx.x, a = threadIdx.x; // 32 threads
    float w1 = sigf(beta1[0]), w2 = sigf(beta2[0]);
    float pA = g_P[0*NNODE*DA + n*DA + a];
    float pF = g_P[1*NNODE*DA + n*DA + a];
    float pD = g_P[2*NNODE*DA + n*DA + a];
    float pP = g_P[3*NNODE*DA + n*DA + a];
    float fb = fus_b[a], fv = fus_v[a];
    float t0 = tanhf(0.5f*pA + 0.5f*pP + fb)*fv;
    float t1 = tanhf(w1*pA + (1.f-w1)*pF + fb)*fv;
    float t2 = tanhf(w2*pA + (1.f-w2)*pD + fb)*fv;
#pragma unroll
    for (int s = 16; s > 0; s >>= 1){
        t0 += __shfl_down_sync(0xffffffffu, t0, s);
        t1 += __shfl_down_sync(0xffffffffu, t1, s);
        t2 += __shfl_down_sync(0xffffffffu, t2, s);
    }
    if (a == 0){ g_scpart[0*NNODE+n]=t0; g_scpart[1*NNODE+n]=t1; g_scpart[2*NNODE+n]=t2; }
}

__global__ void k_finalize(const float* __restrict__ beta1, const float* __restrict__ beta2,
                           const float* __restrict__ W1, const float* __restrict__ b1){
    __shared__ float red[1024];
    __shared__ float sc[3];
    __shared__ float st[6];
    int tid = threadIdx.x;
    for (int k = 0; k < 3; k++){
        red[tid] = (tid < NNODE) ? g_scpart[k*NNODE + tid] : 0.f;
        __syncthreads();
        for (int s = 512; s > 0; s >>= 1){ if (tid < s) red[tid] += red[tid+s]; __syncthreads(); }
        if (tid == 0) sc[k] = red[0] / (float)NNODE;
        __syncthreads();
    }
    red[tid] = (tid < CC) ? W1[tid] : 0.f; __syncthreads();
    for (int s = 512; s > 0; s >>= 1){ if (tid < s) red[tid] += red[tid+s]; __syncthreads(); }
    if (tid == 0) st[0] = red[0]/(float)CC;
    __syncthreads();
    red[tid] = (tid < CC) ? b1[tid] : 0.f; __syncthreads();
    for (int s = 512; s > 0; s >>= 1){ if (tid < s) red[tid] += red[tid+s]; __syncthreads(); }
    if (tid == 0) st[1] = red[0]/(float)CC;
    __syncthreads();
    float dw = 0.f, db = 0.f;
    if (tid < CC){
        dw = W1[tid] - st[0]; db = b1[tid] - st[1];
        g_dWc[tid] = dw; g_dbc[tid] = db;
    }
    red[tid] = dw*dw; __syncthreads();
    for (int s = 512; s > 0; s >>= 1){ if (tid < s) red[tid] += red[tid+s]; __syncthreads(); }
    if (tid == 0) st[2] = red[0]/(float)CC;
    __syncthreads();
    red[tid] = dw*db; __syncthreads();
    for (int s = 512; s > 0; s >>= 1){ if (tid < s) red[tid] += red[tid+s]; __syncthreads(); }
    if (tid == 0) st[3] = red[0]/(float)CC;
    __syncthreads();
    red[tid] = db*db; __syncthreads();
    for (int s = 512; s > 0; s >>= 1){ if (tid < s) red[tid] += red[tid+s]; __syncthreads(); }
    if (tid == 0) st[4] = red[0]/(float)CC;
    __syncthreads();
    if (tid == 0){
        float w1 = sigf(beta1[0]), w2 = sigf(beta2[0]);
        float m = fmaxf(sc[0], fmaxf(sc[1], sc[2]));
        float e0 = expf(sc[0]-m), e1 = expf(sc[1]-m), e2 = expf(sc[2]-m);
        float is = 1.f/(e0+e1+e2);
        float a0 = e0*is, a1 = e1*is, a2 = e2*is;
        g_cons[0] = 0.5f*a0 + w1*a1 + w2*a2;
        g_cons[1] = a1*(1.f-w1);
        g_cons[2] = a2*(1.f-w2);
        g_cons[3] = 0.5f*a0;
        g_cons[4] = st[2];
        g_cons[5] = st[3];
        g_cons[6] = st[4];
    }
    __syncthreads();
    if (tid < NNODE){
        float d = g_cons[0]*g_rs[tid] + g_cons[1]*g_rs[NNODE+tid] + g_cons[2]*g_rs[2*NNODE+tid] + g_cons[3] + 1.0f;
        g_dinv[tid] = rsqrtf(fmaxf(d, 1e-12f));
    }
}

// S_hat into PADDED layout (1000 x 1024, cols >= 1000 zero)
__global__ void k_shat(const float* __restrict__ A, const float* __restrict__ F, const float* __restrict__ D){
    int idx = blockIdx.x*256 + threadIdx.x;
    if (idx >= NNODE*NPAD) return;
    int n = idx >> 10, m = idx & (NPAD-1);
    float v = 0.f;
    if (m < NNODE){
        int src = n*NNODE + m;
        v = g_cons[0]*A[src] + g_cons[1]*F[src] + g_cons[2]*D[src] + g_cons[3]*g_Aadp[src];
        if (n == m) v += 1.0f;
        v *= g_dinv[n]*g_dinv[m];
    }
    g_S[idx] = v;
}

// permute GRU weight rows (g*HG+c -> 3c+g) into combined matrix at column offset
__global__ void k_permW2(const float* __restrict__ W, float* __restrict__ Wp,
                         int K, int dstStride, int colOff){
    int idx = blockIdx.x*256 + threadIdx.x;
    if (idx < G3*K){
        int row = idx / K, k = idx - row*K;
        int g = row / HG, c = row - g*HG;
        Wp[(size_t)(3*c+g)*dstStride + colOff + k] = W[idx];
    }
}

__global__ void k_permB(const float* __restrict__ b0, const float* __restrict__ b1,
                        const float* __restrict__ b2, const float* __restrict__ b3,
                        float* __restrict__ p0, float* __restrict__ p1,
                        float* __restrict__ p2, float* __restrict__ p3){
    int idx = blockIdx.x*256 + threadIdx.x;
    if (idx < G3){
        int g = idx / HG, c = idx - g*HG;
        int d = 3*c+g;
        p0[d] = b0[idx]; p1[d] = b1[idx]; p2[d] = b2[idx]; p3[d] = b3[idx];
    }
}

// GCN layer1 elementwise into PADDED H (1024 rows per bt; rows >= 1000 zero)
__global__ void k_gcn1(const float* __restrict__ g1, const float* __restrict__ bln1,
                       float* __restrict__ H){
    int idx = blockIdx.x*256 + threadIdx.x;
    if (idx >= BT*NPAD*CC) return;
    int row = idx / CC, c = idx - row*CC;
    int nl = row & (NPAD-1);
    int bt = row >> 10;
    float h = 0.f;
    if (nl < NNODE){
        float y = __ldg(&g_Y[bt*NNODE + nl]);
        float diff = y*g_dWc[c] + g_dbc[c];
        float var = y*y*g_cons[4] + 2.f*y*g_cons[5] + g_cons[6];
        h = fmaxf(diff*rsqrtf(var + LN_EPS)*g1[c] + bln1[c], 0.f);
    }
    H[idx] = h;
}

// ---------------- generic NT GEMM (used for S@x only): 64x96, BK=32, FFMA2 ----------------
template<bool GUARD>
__global__ __launch_bounds__(256) void k_gemm_nt(const float* __restrict__ A, int lda,
                          const float* __restrict__ B, int ldb,
                          float* __restrict__ C, int ldc,
                          int M, int N, int K, const float* __restrict__ bias){
    __shared__ __align__(16) float As[64][33];
    __shared__ __align__(16) float Bs[32][98];
    int tid = threadIdx.x;
    int tx = tid & 15, ty = tid >> 4;
    int m0 = blockIdx.y*64, n0 = blockIdx.x*96;
    unsigned long long acc[4][3];
#pragma unroll
    for (int i = 0; i < 4; i++)
#pragma unroll
        for (int p = 0; p < 3; p++) acc[i][p] = 0ULL;
    for (int k0 = 0; k0 < K; k0 += 32){
#pragma unroll
        for (int e = tid; e < 2048; e += 256){
            int r = e >> 5, c = e & 31;
            float v;
            if (GUARD) v = (m0+r < M && k0+c < K) ? A[(size_t)(m0+r)*lda + k0+c] : 0.f;
            else       v = A[(size_t)(m0+r)*lda + k0+c];
            As[r][c] = v;
        }
#pragma unroll
        for (int e = tid; e < 3072; e += 256){
            int j = e >> 5, c = e & 31;
            float v;
            if (GUARD) v = (n0+j < N && k0+c < K) ? B[(size_t)(n0+j)*ldb + k0+c] : 0.f;
            else       v = B[(size_t)(n0+j)*ldb + k0+c];
            Bs[c][j] = v;
        }
        __syncthreads();
#pragma unroll
        for (int kk = 0; kk < 32; kk++){
            unsigned long long a2[4], b2[3];
            const unsigned long long* brow = reinterpret_cast<const unsigned long long*>(&Bs[kk][0]);
#pragma unroll
            for (int i = 0; i < 4; i++) a2[i] = pack2dup(As[ty*4+i][kk]);
#pragma unroll
            for (int p = 0; p < 3; p++) b2[p] = brow[tx*3+p];
#pragma unroll
            for (int i = 0; i < 4; i++)
#pragma unroll
                for (int p = 0; p < 3; p++) fma2(acc[i][p], a2[i], b2[p]);
        }
        __syncthreads();
    }
#pragma unroll
    for (int i = 0; i < 4; i++){
        int gr = m0 + ty*4 + i;
        if (GUARD && gr >= M) continue;
        float v[6];
#pragma unroll
        for (int p = 0; p < 3; p++) unpack2(acc[i][p], v[2*p], v[2*p+1]);
#pragma unroll
        for (int j = 0; j < 6; j++){
            int gc = n0 + tx*6 + j;
            if (GUARD && gc >= N) continue;
            float w = v[j];
            if (bias) w += bias[gc];
            C[(size_t)gr*ldc + gc] = w;
        }
    }
}

// ---------------- S@H: padded, guard-free, 3-stage cp.async pipeline ----------------
// A = g_S (1000x1024 padded, lda=1024), B = H + z*1024*96, C = Z + z*96000.
// Grid: (1, 16, 384). K = 1024 = 32 chunks.
#define STG 5248   // floats per stage: 64*33 + 32*98
__global__ __launch_bounds__(256) void k_gemm_nn_p(const float* __restrict__ Hbase,
                                                   float* __restrict__ Zbase){
    extern __shared__ float dsm[];
    const float* B = Hbase + (size_t)blockIdx.z*(NPAD*CC);
    float* C = Zbase + (size_t)blockIdx.z*(NNODE*CC);
    int tid = threadIdx.x;
    int tx = tid & 15, ty = tid >> 4;
    int m0 = blockIdx.y*64;
    unsigned long long acc[4][3];
#pragma unroll
    for (int i = 0; i < 4; i++)
#pragma unroll
        for (int p = 0; p < 3; p++) acc[i][p] = 0ULL;

    auto load_chunk = [&](int q, int s){
        float* As = dsm + s*STG;
        float* Bs = dsm + s*STG + 2112;
        int k0 = q*32;
#pragma unroll
        for (int e = tid; e < 2048; e += 256){
            int r = e >> 5, c = e & 31;
            int row = m0 + r;
            bool ok = row < NNODE;
            int srow = ok ? row : (NNODE-1);
            cp4z(&As[r*33 + c], g_S + (size_t)srow*NPAD + k0 + c, ok);
        }
#pragma unroll
        for (int e = tid; e < 3072; e += 256){
            int kk = e / 96, j = e - kk*96;
            cp4(&Bs[kk*98 + j], B + (size_t)(k0+kk)*CC + j);
        }
        cp_commit();
    };

    load_chunk(0, 0);
    load_chunk(1, 1);
    for (int q = 0; q < 32; q++){
        if (q < 31) cp_wait<1>(); else cp_wait<0>();
        __syncthreads();
        if (q + 2 < 32) load_chunk(q+2, (q+2)%3);
        int s = q % 3;
        const float* As = dsm + s*STG;
        const float* Bs = dsm + s*STG + 2112;
#pragma unroll
        for (int kk = 0; kk < 32; kk++){
            unsigned long long a2[4], b2[3];
            const unsigned long long* brow = reinterpret_cast<const unsigned long long*>(Bs + kk*98);
#pragma unroll
            for (int i = 0; i < 4; i++) a2[i] = pack2dup(As[(ty*4+i)*33 + kk]);
#pragma unroll
            for (int p = 0; p < 3; p++) b2[p] = brow[tx*3+p];
#pragma unroll
            for (int i = 0; i < 4; i++)
#pragma unroll
                for (int p = 0; p < 3; p++) fma2(acc[i][p], a2[i], b2[p]);
        }
        __syncthreads();
    }
#pragma unroll
    for (int i = 0; i < 4; i++){
        int gr = m0 + ty*4 + i;
        if (gr >= NNODE) continue;
        float v[6];
#pragma unroll
        for (int p = 0; p < 3; p++) unpack2(acc[i][p], v[2*p], v[2*p+1]);
#pragma unroll
        for (int j = 0; j < 6; j++)
            C[(size_t)gr*CC + tx*6 + j] = v[j];
    }
}

// Z @ W2 + b2 -> LN(ln2) -> write in natural (b,t,n,c) order (raw-view reshape semantics)
__global__ __launch_bounds__(256) void k_gemm_nn_ln(const float* __restrict__ A,   // Z, lda=96
                             const float* __restrict__ W2,  // 96x96
                             const float* __restrict__ b2,
                             const float* __restrict__ g2,
                             const float* __restrict__ bln2,
                             float* __restrict__ HS){
    __shared__ __align__(16) float As[64][33];
    __shared__ __align__(16) float Bs[32][98];
    __shared__ float red[64][17];
    int tid = threadIdx.x;
    int tx = tid & 15, ty = tid >> 4;
    int m0 = blockIdx.y*64;
    unsigned long long acc[4][3];
#pragma unroll
    for (int i = 0; i < 4; i++)
#pragma unroll
        for (int p = 0; p < 3; p++) acc[i][p] = 0ULL;
    for (int k0 = 0; k0 < 96; k0 += 32){
#pragma unroll
        for (int e = tid; e < 2048; e += 256){
            int r = e >> 5, c = e & 31;
            As[r][c] = A[(size_t)(m0+r)*96 + k0+c];
        }
#pragma unroll
        for (int e = tid; e < 3072; e += 256){
            int kk = e / 96, j = e - kk*96;
            Bs[kk][j] = W2[(k0+kk)*96 + j];
        }
        __syncthreads();
#pragma unroll
        for (int kk = 0; kk < 32; kk++){
            unsigned long long a2[4], b2[3];
            const unsigned long long* brow = reinterpret_cast<const unsigned long long*>(&Bs[kk][0]);
#pragma unroll
            for (int i = 0; i < 4; i++) a2[i] = pack2dup(As[ty*4+i][kk]);
#pragma unroll
            for (int p = 0; p < 3; p++) b2[p] = brow[tx*3+p];
#pragma unroll
            for (int i = 0; i < 4; i++)
#pragma unroll
                for (int p = 0; p < 3; p++) fma2(acc[i][p], a2[i], b2[p]);
        }
        __syncthreads();
    }
    float v[4][6];
#pragma unroll
    for (int i = 0; i < 4; i++){
#pragma unroll
        for (int p = 0; p < 3; p++) unpack2(acc[i][p], v[i][2*p], v[i][2*p+1]);
#pragma unroll
        for (int j = 0; j < 6; j++) v[i][j] += b2[tx*6+j];
    }
#pragma unroll
    for (int i = 0; i < 4; i++){
        float p = 0.f;
#pragma unroll
        for (int j = 0; j < 6; j++) p += v[i][j];
        red[ty*4+i][tx] = p;
    }
    __syncthreads();
    float mean[4];
#pragma unroll
    for (int i = 0; i < 4; i++){
        float s = 0.f;
#pragma unroll
        for (int q = 0; q < 16; q++) s += red[ty*4+i][q];
        mean[i] = s * (1.0f/96.0f);
    }
    __syncthreads();
#pragma unroll
    for (int i = 0; i < 4; i++){
        float p = 0.f;
#pragma unroll
        for (int j = 0; j < 6; j++){ float d = v[i][j]-mean[i]; p += d*d; }
        red[ty*4+i][tx] = p;
    }
    __syncthreads();
#pragma unroll
    for (int i = 0; i < 4; i++){
        float s = 0.f;
#pragma unroll
        for (int q = 0; q < 16; q++) s += red[ty*4+i][q];
        float rstd = rsqrtf(s*(1.0f/96.0f) + LN_EPS);
        int R = m0 + ty*4 + i;
        size_t base = (size_t)R*96;         // RAW VIEW: identity layout
#pragma unroll
        for (int j = 0; j < 6; j++){
            int col = tx*6 + j;
            HS[base + col] = (v[i][j]-mean[i])*rstd*g2[col] + bln2[col];
        }
    }
}

// Fused GRU step with 3-stage cp.async pipeline (single __syncthreads per chunk).
template<int KH, int KX>
__global__ __launch_bounds__(256) void k_gru_fused(
    const float* __restrict__ Ah, int ldah,      // h_prev rows (lda=0 -> zero buffer)
    const float* __restrict__ Ax, int ldax,      // x_t rows (pre-offset to slice)
    const float* __restrict__ B,                 // combined 576 x (KH+KX)
    const float* __restrict__ bih, const float* __restrict__ bhh,  // permuted
    float* __restrict__ ys){                     // + t*192, row stride 2304
    constexpr int KT = KH + KX;
    constexpr int NCH = KT / 32;
    constexpr int CH_H = KH / 32;
    extern __shared__ float dsm[];
    int tid = threadIdx.x;
    int tx = tid & 15, ty = tid >> 4;
    int m0 = blockIdx.y*64, n0 = blockIdx.x*96;
    unsigned long long ah[4][3], ax[4][3];
#pragma unroll
    for (int i = 0; i < 4; i++)
#pragma unroll
        for (int p = 0; p < 3; p++){ ah[i][p] = 0ULL; ax[i][p] = 0ULL; }

    auto load_chunk = [&](int q, int s){
        float* As = dsm + s*STG;
        float* Bs = dsm + s*STG + 2112;
        const float* Asrc; int ldA; int kof;
        if (q < CH_H){ Asrc = Ah; ldA = ldah; kof = q*32; }
        else         { Asrc = Ax; ldA = ldax; kof = (q-CH_H)*32; }
#pragma unroll
        for (int e = tid; e < 2048; e += 256){
            int r = e >> 5, c = e & 31;
            cp4(&As[r*33 + c], Asrc + (size_t)(m0+r)*ldA + kof + c);
        }
        int bk = q*32;
#pragma unroll
        for (int e = tid; e < 3072; e += 256){
            int j = e >> 5, c = e & 31;
            cp4(&Bs[c*98 + j], B + (size_t)(n0+j)*KT + bk + c);
        }
        cp_commit();
    };

    load_chunk(0, 0);
    load_chunk(1, 1);
#pragma unroll
    for (int q = 0; q < NCH; q++){
        if (q < NCH-1) cp_wait<1>(); else cp_wait<0>();
        __syncthreads();
        if (q + 2 < NCH) load_chunk(q+2, (q+2)%3);
        int s = q % 3;
        const float* As = dsm + s*STG;
        const float* Bs = dsm + s*STG + 2112;
        if (q < CH_H){
#pragma unroll
            for (int kk = 0; kk < 32; kk++){
                unsigned long long a2[4], b2[3];
                const unsigned long long* brow = reinterpret_cast<const unsigned long long*>(Bs + kk*98);
#pragma unroll
                for (int i = 0; i < 4; i++) a2[i] = pack2dup(As[(ty*4+i)*33 + kk]);
#pragma unroll
                for (int p = 0; p < 3; p++) b2[p] = brow[tx*3+p];
#pragma unroll
                for (int i = 0; i < 4; i++)
#pragma unroll
                    for (int p = 0; p < 3; p++) fma2(ah[i][p], a2[i], b2[p]);
            }
        } else {
#pragma unroll
            for (int kk = 0; kk < 32; kk++){
                unsigned long long a2[4], b2[3];
                const unsigned long long* brow = reinterpret_cast<const unsigned long long*>(Bs + kk*98);
#pragma unroll
                for (int i = 0; i < 4; i++) a2[i] = pack2dup(As[(ty*4+i)*33 + kk]);
#pragma unroll
                for (int p = 0; p < 3; p++) b2[p] = brow[tx*3+p];
#pragma unroll
                for (int i = 0; i < 4; i++)
#pragma unroll
                    for (int p = 0; p < 3; p++) fma2(ax[i][p], a2[i], b2[p]);
            }
        }
        __syncthreads();
    }

    int j0 = n0 + tx*6;
    int c0 = j0 / 3;
#pragma unroll
    for (int i = 0; i < 4; i++){
        int row = m0 + ty*4 + i;
        float vh[6], vx[6];
#pragma unroll
        for (int p = 0; p < 3; p++){ unpack2(ah[i][p], vh[2*p], vh[2*p+1]); unpack2(ax[i][p], vx[2*p], vx[2*p+1]); }
#pragma unroll
        for (int p = 0; p < 2; p++){
            int j = j0 + p*3;
            int c = c0 + p;
            float hprev = Ah[(size_t)row*ldah + c];   // lda=0 -> g_zero[c]=0 at t=0
            float r = sigf(vx[p*3]   + bih[j]   + vh[p*3]   + bhh[j]);
            float z = sigf(vx[p*3+1] + bih[j+1] + vh[p*3+1] + bhh[j+1]);
            float nn = tanhf(vx[p*3+2] + bih[j+2] + r*(vh[p*3+2] + bhh[j+2]));
            ys[(size_t)row*2304 + c] = (1.f-z)*nn + z*hprev;
        }
    }
}

// Attention pooling + FC head
__global__ void k_pool(const float* __restrict__ ys, const float* __restrict__ attw,
                       const float* __restrict__ fc1b, const float* __restrict__ fc2b,
                       float* __restrict__ out){
    __shared__ float sOut[12][193];
    __shared__ float sAtt[12];
    __shared__ float sCtx[192];
    __shared__ float sHfc[192];
    __shared__ float red2[16][12];
    int bn = blockIdx.x, tid = threadIdx.x;  // 192 threads
#pragma unroll
    for (int t = 0; t < 12; t++) sOut[t][tid] = ys[(size_t)bn*2304 + t*192 + tid];
    __syncthreads();
    int w = tid >> 5, l = tid & 31;
#pragma unroll
    for (int q = 0; q < 2; q++){
        int t = 2*w + q;
        float p = 0.f;
#pragma unroll
        for (int s = 0; s < 6; s++) p += sOut[t][l + 32*s]*attw[l + 32*s];
#pragma unroll
        for (int s = 16; s > 0; s >>= 1) p += __shfl_down_sync(0xffffffffu, p, s);
        if (l == 0) sAtt[t] = p;
    }
    __syncthreads();
    if (tid == 0){
        float mx = -1e30f;
        for (int t = 0; t < 12; t++) mx = fmaxf(mx, sAtt[t]);
        float s = 0.f;
        for (int t = 0; t < 12; t++){ sAtt[t] = expf(sAtt[t]-mx); s += sAtt[t]; }
        float inv = 1.f/s;
        for (int t = 0; t < 12; t++) sAtt[t] *= inv;
    }
    __syncthreads();
    float c = 0.f;
#pragma unroll
    for (int t = 0; t < 12; t++) c += sAtt[t]*sOut[t][tid];
    sCtx[tid] = c;
    __syncthreads();
    float a0 = 0.f, a1 = 0.f, a2 = 0.f, a3 = 0.f;
#pragma unroll 4
    for (int k = 0; k < 192; k += 4){
        a0 += sCtx[k]  *g_fc1t[(k)*192 + tid];
        a1 += sCtx[k+1]*g_fc1t[(k+1)*192 + tid];
        a2 += sCtx[k+2]*g_fc1t[(k+2)*192 + tid];
        a3 += sCtx[k+3]*g_fc1t[(k+3)*192 + tid];
    }
    sHfc[tid] = gelu_t(fc1b[tid] + ((a0+a1)+(a2+a3)));
    __syncthreads();
    int o = tid % 12, grp = tid / 12;
    float p2 = 0.f;
    for (int j = grp; j < 192; j += 16) p2 += sHfc[j]*g_fc2t[j*12 + o];
    red2[grp][o] = p2;
    __syncthreads();
    if (tid < 12){
        float s = fc2b[tid];
#pragma unroll
        for (int q = 0; q < 16; q++) s += red2[q][tid];
        int b = bn / 1000, n = bn - b*1000;
        out[(size_t)(b*12 + tid)*1000 + n] = s;
    }
}

// ---------------- host launcher ----------------
extern "C" void kernel_launch(void* const* d_in, const int* in_sizes, int n_in,
                              void* d_out, int out_size){
    const float* x      = (const float*)d_in[0];
    const float* A      = (const float*)d_in[1];
    const float* FSP    = (const float*)d_in[2];
    const float* DSP    = (const float*)d_in[3];
    const float* E1     = (const float*)d_in[4];
    const float* E2     = (const float*)d_in[5];
    const float* fus_W  = (const float*)d_in[6];
    const float* fus_b  = (const float*)d_in[7];
    const float* fus_v  = (const float*)d_in[8];
    const float* beta1  = (const float*)d_in[9];
    const float* beta2  = (const float*)d_in[10];
    const float* gcn_W1 = (const float*)d_in[11];
    const float* gcn_b1 = (const float*)d_in[12];
    const float* ln1_g  = (const float*)d_in[13];
    const float* ln1_b  = (const float*)d_in[14];
    const float* gcn_W2 = (const float*)d_in[15];
    const float* gcn_b2 = (const float*)d_in[16];
    const float* ln2_g  = (const float*)d_in[17];
    const float* ln2_b  = (const float*)d_in[18];
    const float* Wih0   = (const float*)d_in[19];
    const float* Whh0   = (const float*)d_in[20];
    const float* bih0   = (const float*)d_in[21];
    const float* bhh0   = (const float*)d_in[22];
    const float* Wih1   = (const float*)d_in[23];
    const float* Whh1   = (const float*)d_in[24];
    const float* bih1   = (const float*)d_in[25];
    const float* bhh1   = (const float*)d_in[26];
    const float* att_w  = (const float*)d_in[27];
    const float* fc1_W  = (const float*)d_in[28];
    const float* fc1_b  = (const float*)d_in[29];
    const float* fc2_W  = (const float*)d_in[30];
    const float* fc2_b  = (const float*)d_in[31];
    float* out = (float*)d_out;

    float *p_big, *p_Wt, *p_Y, *p_zero, *p_Wc0, *p_Wc1;
    float *p_bih0p, *p_bhh0p, *p_bih1p, *p_bhh1p;
    float *p_fc1t, *p_fc2t;
    cudaGetSymbolAddress((void**)&p_big, g_big);
    cudaGetSymbolAddress((void**)&p_Wt, g_Wt);
    cudaGetSymbolAddress((void**)&p_Y, g_Y);
    cudaGetSymbolAddress((void**)&p_zero, g_zero);
    cudaGetSymbolAddress((void**)&p_Wc0, g_Wc0);
    cudaGetSymbolAddress((void**)&p_Wc1, g_Wc1);
    cudaGetSymbolAddress((void**)&p_bih0p, g_bih0p);
    cudaGetSymbolAddress((void**)&p_bhh0p, g_bhh0p);
    cudaGetSymbolAddress((void**)&p_bih1p, g_bih1p);
    cudaGetSymbolAddress((void**)&p_bhh1p, g_bhh1p);
    cudaGetSymbolAddress((void**)&p_fc1t, g_fc1t);
    cudaGetSymbolAddress((void**)&p_fc2t, g_fc2t);

    float* p_HS  = p_big + OFF_HS;
    float* p_H   = p_big + OFF_H;
    float* p_Z   = p_big + OFF_Z;
    float* p_ys0 = p_big + OFF_YS0;
    float* p_ys1 = p_big + OFF_YS1;

    // opt-in to >48KB dynamic smem for pipelined kernels (attribute set, not allocation)
    static bool attr_done = false;
    const int DSM = 3*STG*4;
    if (!attr_done){
        cudaFuncSetAttribute(k_gemm_nn_p, cudaFuncAttributeMaxDynamicSharedMemorySize, DSM);
        cudaFuncSetAttribute(k_gru_fused<HG, CC>, cudaFuncAttributeMaxDynamicSharedMemorySize, DSM);
        cudaFuncSetAttribute(k_gru_fused<HG, HG>, cudaFuncAttributeMaxDynamicSharedMemorySize, DSM);
        attr_done = true;
    }

    // graph construction
    k_transp<<<(DA*NNODE+255)/256, 256>>>(fus_W, p_Wt, DA, NNODE);
    k_rowsums<<<NNODE, 256>>>(A, FSP, DSP);
    k_adapt<<<NNODE, 256>>>(E1, E2);
    k_proj<<<NNODE, 128>>>(A, FSP, DSP);
    k_scorepart<<<NNODE, 32>>>(fus_b, fus_v, beta1, beta2);
    k_finalize<<<1, 1024>>>(beta1, beta2, gcn_W1, gcn_b1);
    k_shat<<<(NNODE*NPAD+255)/256, 256>>>(A, FSP, DSP);

    // weight prep: combined permuted GRU weights + permuted biases
    k_permW2<<<(G3*HG+255)/256, 256>>>(Whh0, p_Wc0, HG, HG+CC, 0);
    k_permW2<<<(G3*CC+255)/256, 256>>>(Wih0, p_Wc0, CC, HG+CC, HG);
    k_permW2<<<(G3*HG+255)/256, 256>>>(Whh1, p_Wc1, HG, HG+HG, 0);
    k_permW2<<<(G3*HG+255)/256, 256>>>(Wih1, p_Wc1, HG, HG+HG, HG);
    k_permB<<<(G3+255)/256, 256>>>(bih0, bhh0, bih1, bhh1, p_bih0p, p_bhh0p, p_bih1p, p_bhh1p);
    k_transp<<<(HG*HG+255)/256, 256>>>(fc1_W, p_fc1t, HG, HG);
    k_transp<<<(HOR*HG+255)/256, 256>>>(fc2_W, p_fc2t, HOR, HG);

    // GCN
    {   // Y[bt,n] = sum_m x[bt,m] * S[n,m]  (uses padded S rows with lda=NPAD)
        dim3 g((NNODE+95)/96, (BT+63)/64);
        k_gemm_nt<true><<<g, 256>>>(x, NNODE, p_big + OFF_HS /*unused dummy*/, 0, p_Y, NNODE, BT, NNODE, NNODE, nullptr);
    }
    // NOTE: the dummy above is replaced by the real call below (S padded):
    {   dim3 g((NNODE+95)/96, (BT+63)/64);
        float* p_S; cudaGetSymbolAddress((void**)&p_S, g_S);
        k_gemm_nt<true><<<g, 256>>>(x, NNODE, p_S, NPAD, p_Y, NNODE, BT, NNODE, NNODE, nullptr);
    }
    k_gcn1<<<(BT*NPAD*CC+255)/256, 256>>>(ln1_g, ln1_b, p_H);
    {   dim3 g(1, 16, BT);
        k_gemm_nn_p<<<g, 256, DSM>>>(p_H, p_Z);
    }
    {   dim3 g(1, (BT*NNODE)/64);
        k_gemm_nn_ln<<<g, 256>>>(p_Z, gcn_W2, gcn_b2, ln2_g, ln2_b, p_HS);
    }

    // GRU layer 0 (fused x-projection, KX=96 from HS raw-view rows)
    for (int t = 0; t < TT; t++){
        const float* hA = (t == 0) ? p_zero : (p_ys0 + (size_t)(t-1)*HG);
        int ldah = (t == 0) ? 0 : TT*HG;
        dim3 g(G3/96, BNR/64);
        k_gru_fused<HG, CC><<<g, 256, DSM>>>(hA, ldah, p_HS + (size_t)t*CC, TT*CC,
                                        p_Wc0, p_bih0p, p_bhh0p, p_ys0 + (size_t)t*HG);
    }
    // GRU layer 1 (fused x-projection, KX=192 from ys0 rows)
    for (int t = 0; t < TT; t++){
        const float* hA = (t == 0) ? p_zero : (p_ys1 + (size_t)(t-1)*HG);
        int ldah = (t == 0) ? 0 : TT*HG;
        dim3 g(G3/96, BNR/64);
        k_gru_fused<HG, HG><<<g, 256, DSM>>>(hA, ldah, p_ys0 + (size_t)t*HG, TT*HG,
                                        p_Wc1, p_bih1p, p_bhh1p, p_ys1 + (size_t)t*HG);
    }

    // pooling + head
    k_pool<<<BNR, 192>>>(p_ys1, att_w, fc1_b, fc2_b, out);
}